// round 6
// baseline (speedup 1.0000x reference)
#include <cuda_runtime.h>
#include <cuda_bf16.h>
#include <cstdint>
#include <math.h>

#define B_    8
#define S_    2048
#define HID_  1024
#define NH_   16
#define HD_   64
#define SP_   1024
#define NQKV_ 3072

// ---------------- scratch ----------------------------------------------------
__device__ float g_a [B_*S_*HID_];        // tf32-rounded hidden
__device__ float g_w [NQKV_*HID_];        // tf32-rounded Wqkv
__device__ float g_q [B_*S_*HID_];        // q pre-pool [B,S,HID]
__device__ float g_k [B_*NH_*S_*HD_];     // k head-major (roped)
__device__ float g_v [B_*NH_*S_*HD_];     // v head-major
__device__ float g_qh[B_*NH_*SP_*HD_];    // pooled+roped q
__device__ int   g_len[B_];

// ---------------- helpers -----------------------------------------------------
__device__ __forceinline__ unsigned f2tf(float x) {
    unsigned r; asm("cvt.rna.tf32.f32 %0, %1;" : "=r"(r) : "f"(x)); return r;
}
__device__ __forceinline__ void mma_tf32(float* d,
        unsigned a0, unsigned a1, unsigned a2, unsigned a3,
        unsigned b0, unsigned b1) {
    asm volatile("mma.sync.aligned.m16n8k8.row.col.f32.tf32.tf32.f32 "
        "{%0,%1,%2,%3},{%4,%5,%6,%7},{%8,%9},{%0,%1,%2,%3};\n"
        : "+f"(d[0]), "+f"(d[1]), "+f"(d[2]), "+f"(d[3])
        : "r"(a0), "r"(a1), "r"(a2), "r"(a3), "r"(b0), "r"(b1));
}
__device__ __forceinline__ uint32_t smem_u32(const void* p) {
    uint32_t a;
    asm("{ .reg .u64 t; cvta.to.shared.u64 t, %1; cvt.u32.u64 %0, t; }"
        : "=r"(a) : "l"(p));
    return a;
}
__device__ __forceinline__ void cp16(uint32_t saddr, const void* gptr) {
    asm volatile("cp.async.cg.shared.global [%0], [%1], 16;"
                 :: "r"(saddr), "l"(gptr));
}
__device__ __forceinline__ void cp_commit() {
    asm volatile("cp.async.commit_group;");
}
template <int N>
__device__ __forceinline__ void cp_wait() {
    asm volatile("cp.async.wait_group %0;" :: "n"(N));
}

// ---------------- kernel 1: tf32 pre-round of A & W, plus lengths -------------
#define A4_ (B_*S_*HID_/4)
#define W4_ (NQKV_*HID_/4)
__global__ void cvtlen_kernel(const float* __restrict__ hidden,
                              const float* __restrict__ W,
                              const void*  __restrict__ mask) {
    int i = blockIdx.x * 256 + threadIdx.x;
    if (i < A4_) {
        float4 v = ((const float4*)hidden)[i];
        ((uint4*)g_a)[i] = make_uint4(f2tf(v.x), f2tf(v.y), f2tf(v.z), f2tf(v.w));
    } else {
        int j = i - A4_;
        if (j < W4_) {
            float4 v = ((const float4*)W)[j];
            ((uint4*)g_w)[j] = make_uint4(f2tf(v.x), f2tf(v.y), f2tf(v.z), f2tf(v.w));
        }
    }
    if (blockIdx.x == 0) {
        __shared__ int sred[256];
        const int* mi = (const int*)mask;
        int w = mi[16];
        int mode = (w == 1) ? 0 : ((w == 0x3F800000) ? 1 : 2);
        for (int b = 0; b < B_; b++) {
            int cnt = 0;
            for (int s = threadIdx.x; s < S_; s += 256) {
                int v;
                if (mode == 0)      v = (mi[b*S_+s] != 0);
                else if (mode == 1) v = (((const float*)mask)[b*S_+s] != 0.0f);
                else                v = (((const unsigned char*)mask)[b*S_+s] != 0);
                cnt += v;
            }
            sred[threadIdx.x] = cnt;
            __syncthreads();
            for (int st = 128; st > 0; st >>= 1) {
                if (threadIdx.x < st) sred[threadIdx.x] += sred[threadIdx.x + st];
                __syncthreads();
            }
            if (threadIdx.x == 0) g_len[b] = sred[0];
            __syncthreads();
        }
    }
}

// ---------------- kernel 2: QKV GEMM, tf32 mma.sync + cp.async pipeline -------
// M=16384, N=3072, K=1024.  Block 128x128, BK=32, 3 stages, 8 warps (2x4),
// warp tile 64x32. Inputs pre-rounded to tf32 (g_a/g_w): no CVT in loop.
#define APITCH 36            // %32==4 -> conflict-free fragment LDS
#define ST_    3
#define STAGE_ELEMS (128*APITCH)
#define GEMM_SMEM (2*ST_*STAGE_ELEMS*4)   // 110592 B
__global__ __launch_bounds__(256, 2) void qkv_gemm_cp(const float* __restrict__ bias) {
    extern __shared__ unsigned smb[];
    unsigned* As = smb;                    // [ST_][128*APITCH]
    unsigned* Bs = smb + ST_*STAGE_ELEMS;
    const int bm = blockIdx.y, bn = blockIdx.x, tid = threadIdx.x;
    const int warp = tid >> 5, lane = tid & 31;
    const int wm = warp >> 2, wn = warp & 3;
    const int g = lane >> 2, c = lane & 3;
    const float* Ab = g_a + (size_t)bm * 128 * HID_;
    const float* Wb = g_w + (size_t)bn * 128 * HID_;
    const uint32_t as_base = smem_u32(As);
    const uint32_t bs_base = smem_u32(Bs);
    const int lrow = tid >> 1;             // 0..127
    const int lc4  = (tid & 1) * 16;       // 0 or 16 (float index), 2 cp16 each

    // issue one stage's loads (A: 128x32 floats, B same; 8 cp16 per thread)
#define ISSUE(st, kt) do {                                                       \
        uint32_t ab = as_base + (st)*STAGE_ELEMS*4;                              \
        uint32_t bb = bs_base + (st)*STAGE_ELEMS*4;                              \
        int kof = (kt)*32;                                                       \
        _Pragma("unroll")                                                        \
        for (int q8 = 0; q8 < 2; q8++) {                                         \
            int col = lc4 + q8*4 + ((tid & 1) ? -8 : 0) + ((tid&1)?8:0);         \
            (void)col;                                                           \
        }                                                                        \
        _Pragma("unroll")                                                        \
        for (int q8 = 0; q8 < 2; q8++) {                                         \
            int fc = lc4 + q8*8;   /* 0,8 or 16,24 */                            \
            cp16(ab + (lrow*APITCH + fc)*4, Ab + (size_t)lrow*HID_ + kof + fc);  \
            cp16(ab + (lrow*APITCH + fc + 4)*4, Ab + (size_t)lrow*HID_ + kof + fc + 4); \
            cp16(bb + (lrow*APITCH + fc)*4, Wb + (size_t)lrow*HID_ + kof + fc);  \
            cp16(bb + (lrow*APITCH + fc + 4)*4, Wb + (size_t)lrow*HID_ + kof + fc + 4); \
        }                                                                        \
    } while (0)

    float acc[4][4][4];
#pragma unroll
    for (int i = 0; i < 4; i++)
#pragma unroll
        for (int j = 0; j < 4; j++)
#pragma unroll
            for (int r = 0; r < 4; r++) acc[i][j][r] = 0.0f;

    ISSUE(0, 0); cp_commit();
    ISSUE(1, 1); cp_commit();

    for (int kt = 0; kt < 32; kt++) {
        if (kt < 31) cp_wait<1>(); else cp_wait<0>();
        __syncthreads();
        if (kt + 2 < 32) { ISSUE((kt + 2) % ST_, kt + 2); cp_commit(); }

        const unsigned* Ast = As + (kt % ST_) * STAGE_ELEMS;
        const unsigned* Bst = Bs + (kt % ST_) * STAGE_ELEMS;
#pragma unroll
        for (int ks = 0; ks < 4; ks++) {
            const int k0 = ks * 8;
            unsigned a[4][4], bfr[4][2];
#pragma unroll
            for (int i = 0; i < 4; i++) {
                int r = wm*64 + i*16 + g;
                a[i][0] = Ast[r*APITCH + k0 + c];
                a[i][1] = Ast[(r+8)*APITCH + k0 + c];
                a[i][2] = Ast[r*APITCH + k0 + 4 + c];
                a[i][3] = Ast[(r+8)*APITCH + k0 + 4 + c];
            }
#pragma unroll
            for (int j = 0; j < 4; j++) {
                int n = wn*32 + j*8 + g;
                bfr[j][0] = Bst[n*APITCH + k0 + c];
                bfr[j][1] = Bst[n*APITCH + k0 + 4 + c];
            }
#pragma unroll
            for (int i = 0; i < 4; i++)
#pragma unroll
                for (int j = 0; j < 4; j++)
                    mma_tf32(acc[i][j], a[i][0], a[i][1], a[i][2], a[i][3],
                             bfr[j][0], bfr[j][1]);
        }
    }

    // epilogue: bias + scatter to q / k / v layouts
#pragma unroll
    for (int i = 0; i < 4; i++) {
#pragma unroll
        for (int hh = 0; hh < 2; hh++) {
            int m = bm*128 + wm*64 + i*16 + hh*8 + g;
            int bb2 = m >> 11;
            int s  = m & 2047;
#pragma unroll
            for (int j = 0; j < 4; j++) {
                int n = bn*128 + wn*32 + j*8 + 2*c;
                float v0 = acc[i][j][hh*2+0] + bias[n];
                float v1 = acc[i][j][hh*2+1] + bias[n+1];
                if (n < 1024) {
                    float* p = &g_q[((size_t)(bb2*S_+s))*HID_ + n];
                    p[0] = v0; p[1] = v1;
                } else if (n < 2048) {
                    int nn = n - 1024, hhd = nn >> 6, dd = nn & 63;
                    float* p = &g_k[(((size_t)(bb2*NH_+hhd))*S_ + s)*HD_ + dd];
                    p[0] = v0; p[1] = v1;
                } else {
                    int nn = n - 2048, hhd = nn >> 6, dd = nn & 63;
                    float* p = &g_v[(((size_t)(bb2*NH_+hhd))*S_ + s)*HD_ + dd];
                    p[0] = v0; p[1] = v1;
                }
            }
        }
    }
}

// ---------------- kernel 3: fused RoPE-K + pool+RoPE-Q ------------------------
#define RK_THREADS (B_*NH_*S_*32)
__global__ void ropepool_kernel() {
    int idx = blockIdx.x * blockDim.x + threadIdx.x;
    if (idx < RK_THREADS) {
        int i  = idx & 31;
        int s  = (idx >> 5) & (S_ - 1);
        int bh = idx >> 16;
        float theta = __expf(-(float)i * (9.210340371976184f / 32.0f));
        float ang = (float)s * theta;
        float sn, cs;
        sincosf(ang, &sn, &cs);
        float2* p = (float2*)(g_k + ((size_t)bh*S_ + s)*HD_) + i;
        float2 x = *p;
        float2 o;
        o.x = x.x*cs - x.y*sn;
        o.y = x.y*cs + x.x*sn;
        *p = o;
    } else {
        int id2 = idx - RK_THREADS;
        int i  = id2 & 31;
        int p  = (id2 >> 5) & (SP_ - 1);
        int bh = id2 >> 15;
        int b = bh >> 4, h = bh & 15;
        int len = g_len[b];
        int s0 = 2 * p;
        int c0 = (s0 < len), c1 = (s0 + 1 < len);
        float norm = (c0 + c1 > 0) ? (float)(c0 + c1) : 1.0f;
        const float2* q0 = (const float2*)(g_q + ((size_t)(b*S_+s0  ))*HID_ + h*HD_) + i;
        const float2* q1 = (const float2*)(g_q + ((size_t)(b*S_+s0+1))*HID_ + h*HD_) + i;
        float2 a = c0 ? *q0 : make_float2(0.f, 0.f);
        float2 c = c1 ? *q1 : make_float2(0.f, 0.f);
        float x0 = (a.x + c.x) / norm;
        float x1 = (a.y + c.y) / norm;
        float theta = __expf(-(float)i * (9.210340371976184f / 32.0f));
        float ang = (float)p * theta;
        float sn, cs;
        sincosf(ang, &sn, &cs);
        float2 o;
        o.x = x0*cs - x1*sn;
        o.y = x1*cs + x0*sn;
        ((float2*)(g_qh + ((size_t)bh*SP_ + p)*HD_))[i] = o;
    }
}

// ---------------- kernel 4: flash attention, tf32 mma.sync --------------------
#define QP 68
#define VP 72
#define PP 132
__global__ __launch_bounds__(256, 1) void attn_tc(float* __restrict__ out) {
    extern __shared__ unsigned sm[];
    unsigned* Qs = sm;
    unsigned* Ks = Qs + 128*QP;
    unsigned* Vs = Ks + 128*QP;
    unsigned* Ps = Vs + 128*VP;
    float*   red = (float*)(Ps + 128*PP);

    const int qt = blockIdx.x, h = blockIdx.y, b = blockIdx.z;
    const int len = g_len[b];
    const int tid = threadIdx.x, warp = tid >> 5, lane = tid & 31;
    const int wm = warp >> 2, wn = warp & 3;
    const int g = lane >> 2, c = lane & 3;

    const float* Qg = g_qh + ((size_t)(b*NH_+h)*SP_ + qt*128)*HD_;
    for (int t = tid; t < 128*16; t += 256) {
        int r = t >> 4, c4 = t & 15;
        float4 v = ((const float4*)(Qg + r*HD_))[c4];
        *(uint4*)&Qs[r*QP + c4*4] = make_uint4(
            f2tf(v.x*0.125f), f2tf(v.y*0.125f), f2tf(v.z*0.125f), f2tf(v.w*0.125f));
    }

    float O[4][2][4];
    float m[4][2], l[4][2];
#pragma unroll
    for (int i = 0; i < 4; i++)
#pragma unroll
        for (int hh = 0; hh < 2; hh++) {
            m[i][hh] = -1e30f; l[i][hh] = 0.0f;
            O[i][0][hh*2] = O[i][0][hh*2+1] = 0.0f;
            O[i][1][hh*2] = O[i][1][hh*2+1] = 0.0f;
        }
    __syncthreads();

    const float* Kg = g_k + (size_t)(b*NH_+h)*S_*HD_;
    const float* Vg = g_v + (size_t)(b*NH_+h)*S_*HD_;
    const int ntiles = (len + 127) >> 7;

    for (int kt = 0; kt < ntiles; kt++) {
        for (int t = tid; t < 128*16; t += 256) {
            int r = t >> 4, c4 = t & 15;
            float4 kv = ((const float4*)(Kg + (size_t)(kt*128+r)*HD_))[c4];
            *(uint4*)&Ks[r*QP + c4*4] = make_uint4(f2tf(kv.x), f2tf(kv.y), f2tf(kv.z), f2tf(kv.w));
            float4 vv = ((const float4*)(Vg + (size_t)(kt*128+r)*HD_))[c4];
            *(uint4*)&Vs[r*VP + c4*4] = make_uint4(f2tf(vv.x), f2tf(vv.y), f2tf(vv.z), f2tf(vv.w));
        }
        __syncthreads();

        float s[4][4][4];
#pragma unroll
        for (int i = 0; i < 4; i++)
#pragma unroll
            for (int j = 0; j < 4; j++)
#pragma unroll
                for (int r = 0; r < 4; r++) s[i][j][r] = 0.0f;

#pragma unroll
        for (int ks = 0; ks < 8; ks++) {
            const int k0 = ks * 8;
            unsigned a[4][4];
#pragma unroll
            for (int i = 0; i < 4; i++) {
                int r = wm*64 + i*16 + g;
                a[i][0] = Qs[r*QP + k0 + c];
                a[i][1] = Qs[(r+8)*QP + k0 + c];
                a[i][2] = Qs[r*QP + k0 + 4 + c];
                a[i][3] = Qs[(r+8)*QP + k0 + 4 + c];
            }
#pragma unroll
            for (int j = 0; j < 4; j++) {
                int n = wn*32 + j*8 + g;
                unsigned b0 = Ks[n*QP + k0 + c];
                unsigned b1 = Ks[n*QP + k0 + 4 + c];
#pragma unroll
                for (int i = 0; i < 4; i++)
                    mma_tf32(s[i][j], a[i][0], a[i][1], a[i][2], a[i][3], b0, b1);
            }
        }

        if (kt == ntiles - 1 && (len & 127)) {
#pragma unroll
            for (int j = 0; j < 4; j++) {
#pragma unroll
                for (int cc = 0; cc < 2; cc++) {
                    int kcol = kt*128 + wn*32 + j*8 + 2*c + cc;
                    if (kcol >= len) {
#pragma unroll
                        for (int i = 0; i < 4; i++) {
                            s[i][j][cc] = -1e30f;
                            s[i][j][2+cc] = -1e30f;
                        }
                    }
                }
            }
        }

        float tmax[4][2];
#pragma unroll
        for (int i = 0; i < 4; i++)
#pragma unroll
            for (int hh = 0; hh < 2; hh++) {
                float mx = s[i][0][hh*2];
                mx = fmaxf(mx, s[i][0][hh*2+1]);
#pragma unroll
                for (int j = 1; j < 4; j++) {
                    mx = fmaxf(mx, s[i][j][hh*2]);
                    mx = fmaxf(mx, s[i][j][hh*2+1]);
                }
                mx = fmaxf(mx, __shfl_xor_sync(0xffffffffu, mx, 1));
                mx = fmaxf(mx, __shfl_xor_sync(0xffffffffu, mx, 2));
                tmax[i][hh] = mx;
            }
        if (c == 0) {
#pragma unroll
            for (int i = 0; i < 4; i++)
#pragma unroll
                for (int hh = 0; hh < 2; hh++)
                    red[(wm*64 + i*16 + hh*8 + g)*4 + wn] = tmax[i][hh];
        }
        __syncthreads();

        float corr[4][2], rs[4][2];
#pragma unroll
        for (int i = 0; i < 4; i++)
#pragma unroll
            for (int hh = 0; hh < 2; hh++) {
                int row = wm*64 + i*16 + hh*8 + g;
                float mx = fmaxf(fmaxf(red[row*4+0], red[row*4+1]),
                                 fmaxf(red[row*4+2], red[row*4+3]));
                float mnew = fmaxf(m[i][hh], mx);
                float cr = __expf(m[i][hh] - mnew);
                corr[i][hh] = cr;
                m[i][hh] = mnew;
                float r = 0.0f;
#pragma unroll
                for (int j = 0; j < 4; j++) {
                    float e0 = __expf(s[i][j][hh*2]   - mnew);
                    float e1 = __expf(s[i][j][hh*2+1] - mnew);
                    r += e0 + e1;
                    *(uint2*)&Ps[row*PP + wn*32 + j*8 + 2*c] =
                        make_uint2(f2tf(e0), f2tf(e1));
                }
                r += __shfl_xor_sync(0xffffffffu, r, 1);
                r += __shfl_xor_sync(0xffffffffu, r, 2);
                rs[i][hh] = r;
                O[i][0][hh*2]   *= cr;  O[i][0][hh*2+1] *= cr;
                O[i][1][hh*2]   *= cr;  O[i][1][hh*2+1] *= cr;
            }
        __syncthreads();
        if (c == 0) {
#pragma unroll
            for (int i = 0; i < 4; i++)
#pragma unroll
                for (int hh = 0; hh < 2; hh++)
                    red[(wm*64 + i*16 + hh*8 + g)*4 + wn] = rs[i][hh];
        }
        __syncthreads();
#pragma unroll
        for (int i = 0; i < 4; i++)
#pragma unroll
            for (int hh = 0; hh < 2; hh++) {
                int row = wm*64 + i*16 + hh*8 + g;
                float sum = red[row*4+0] + red[row*4+1] + red[row*4+2] + red[row*4+3];
                l[i][hh] = l[i][hh]*corr[i][hh] + sum;
            }

#pragma unroll
        for (int ks = 0; ks < 16; ks++) {
            const int k0 = ks * 8;
            unsigned a[4][4];
#pragma unroll
            for (int i = 0; i < 4; i++) {
                int row = wm*64 + i*16 + g;
                a[i][0] = Ps[row*PP + k0 + c];
                a[i][1] = Ps[(row+8)*PP + k0 + c];
                a[i][2] = Ps[row*PP + k0 + 4 + c];
                a[i][3] = Ps[(row+8)*PP + k0 + 4 + c];
            }
#pragma unroll
            for (int j = 0; j < 2; j++) {
                int n0 = wn*16 + j*8;
                unsigned b0 = Vs[(k0 + c)*VP + n0 + g];
                unsigned b1 = Vs[(k0 + 4 + c)*VP + n0 + g];
#pragma unroll
                for (int i = 0; i < 4; i++)
                    mma_tf32(O[i][j], a[i][0], a[i][1], a[i][2], a[i][3], b0, b1);
            }
        }
        __syncthreads();
    }

#pragma unroll
    for (int i = 0; i < 4; i++)
#pragma unroll
        for (int hh = 0; hh < 2; hh++) {
            int row = wm*64 + i*16 + hh*8 + g;
            int qg = qt*128 + row;
            float inv = (2*qg < len) ? (1.0f / l[i][hh]) : 0.0f;
#pragma unroll
            for (int j = 0; j < 2; j++) {
                int col = wn*16 + j*8 + 2*c;
                float2 o = make_float2(O[i][j][hh*2]*inv, O[i][j][hh*2+1]*inv);
                *(float2*)&out[((size_t)(b*SP_ + qg))*(NH_*HD_) + h*HD_ + col] = o;
            }
        }
}

// ---------------- launcher ----------------------------------------------------
extern "C" void kernel_launch(void* const* d_in, const int* in_sizes, int n_in,
                              void* d_out, int out_size) {
    const float* hidden = (const float*)d_in[0];
    const void*  mask   = d_in[1];
    const float* W      = (const float*)d_in[2];
    const float* bias   = (const float*)d_in[3];
    float* out = (float*)d_out;

    cvtlen_kernel<<<(A4_ + W4_) / 256, 256>>>(hidden, W, mask);

    cudaFuncSetAttribute(qkv_gemm_cp, cudaFuncAttributeMaxDynamicSharedMemorySize, GEMM_SMEM);
    dim3 gg(NQKV_/128, (B_*S_)/128);   // (24, 128)
    qkv_gemm_cp<<<gg, 256, GEMM_SMEM>>>(bias);

    ropepool_kernel<<<(RK_THREADS + B_*NH_*SP_*32) / 256, 256>>>();

    const int attn_smem = (128*QP + 128*QP + 128*VP + 128*PP) * 4 + 128*4*4;
    cudaFuncSetAttribute(attn_tc, cudaFuncAttributeMaxDynamicSharedMemorySize, attn_smem);
    dim3 ga(SP_/128, NH_, B_);
    attn_tc<<<ga, 256, attn_smem>>>(out);
}

// round 7
// speedup vs baseline: 2.2839x; 2.2839x over previous
#include <cuda_runtime.h>
#include <cuda_fp16.h>
#include <cstdint>
#include <math.h>

#define B_    8
#define S_    2048
#define HID_  1024
#define NH_   16
#define HD_   64
#define SP_   1024
#define NQKV_ 3072
#define QSCALE 0.18033688f   // 0.125 * log2(e)

// ---------------- scratch ----------------------------------------------------
__device__ __half g_ah[B_*S_*HID_];       // half hidden
__device__ __half g_wh[NQKV_*HID_];       // half Wqkv
__device__ float  g_q [B_*S_*HID_];       // q pre-pool f32
__device__ float  g_k [B_*NH_*S_*HD_];    // k head-major f32 (pre-rope)
__device__ __half g_kh[B_*NH_*S_*HD_];    // roped K half
__device__ __half g_vh[B_*NH_*S_*HD_];    // V half
__device__ __half g_qh[B_*NH_*SP_*HD_];   // pooled+roped+scaled Q half
__device__ int    g_len[B_];

// ---------------- helpers -----------------------------------------------------
__device__ __forceinline__ void mma_f16(float* d,
        unsigned a0, unsigned a1, unsigned a2, unsigned a3,
        unsigned b0, unsigned b1) {
    asm volatile("mma.sync.aligned.m16n8k16.row.col.f32.f16.f16.f32 "
        "{%0,%1,%2,%3},{%4,%5,%6,%7},{%8,%9},{%0,%1,%2,%3};\n"
        : "+f"(d[0]), "+f"(d[1]), "+f"(d[2]), "+f"(d[3])
        : "r"(a0), "r"(a1), "r"(a2), "r"(a3), "r"(b0), "r"(b1));
}
__device__ __forceinline__ unsigned pk(float lo, float hi) {
    __half2 h = __floats2half2_rn(lo, hi);
    return *reinterpret_cast<unsigned*>(&h);
}
__device__ __forceinline__ uint32_t smem_u32(const void* p) {
    uint32_t a;
    asm("{ .reg .u64 t; cvta.to.shared.u64 t, %1; cvt.u32.u64 %0, t; }"
        : "=r"(a) : "l"(p));
    return a;
}
__device__ __forceinline__ void cp16(uint32_t saddr, const void* gptr) {
    asm volatile("cp.async.cg.shared.global [%0], [%1], 16;"
                 :: "r"(saddr), "l"(gptr));
}
__device__ __forceinline__ void cp_commit() { asm volatile("cp.async.commit_group;"); }
template <int N>
__device__ __forceinline__ void cp_wait() {
    asm volatile("cp.async.wait_group %0;" :: "n"(N));
}
__device__ __forceinline__ void ldsm2t(unsigned& r0, unsigned& r1, uint32_t addr) {
    asm volatile("ldmatrix.sync.aligned.m8n8.x2.trans.shared.b16 {%0,%1}, [%2];"
        : "=r"(r0), "=r"(r1) : "r"(addr));
}

// ---------------- kernel 1: half pre-convert of A & W, plus lengths -----------
#define A4_ (B_*S_*HID_/4)
#define W4_ (NQKV_*HID_/4)
__global__ void cvtlen_kernel(const float* __restrict__ hidden,
                              const float* __restrict__ W,
                              const void*  __restrict__ mask) {
    int i = blockIdx.x * 256 + threadIdx.x;
    if (i < A4_) {
        float4 v = ((const float4*)hidden)[i];
        ((uint2*)g_ah)[i] = make_uint2(pk(v.x, v.y), pk(v.z, v.w));
    } else {
        int j = i - A4_;
        if (j < W4_) {
            float4 v = ((const float4*)W)[j];
            ((uint2*)g_wh)[j] = make_uint2(pk(v.x, v.y), pk(v.z, v.w));
        }
    }
    if (blockIdx.x == 0) {
        __shared__ int sred[256];
        const int* mi = (const int*)mask;
        int w = mi[16];
        int mode = (w == 1) ? 0 : ((w == 0x3F800000) ? 1 : 2);
        for (int b = 0; b < B_; b++) {
            int cnt = 0;
            for (int s = threadIdx.x; s < S_; s += 256) {
                int v;
                if (mode == 0)      v = (mi[b*S_+s] != 0);
                else if (mode == 1) v = (((const float*)mask)[b*S_+s] != 0.0f);
                else                v = (((const unsigned char*)mask)[b*S_+s] != 0);
                cnt += v;
            }
            sred[threadIdx.x] = cnt;
            __syncthreads();
            for (int st = 128; st > 0; st >>= 1) {
                if (threadIdx.x < st) sred[threadIdx.x] += sred[threadIdx.x + st];
                __syncthreads();
            }
            if (threadIdx.x == 0) g_len[b] = sred[0];
            __syncthreads();
        }
    }
}

// ---------------- kernel 2: QKV GEMM, fp16 m16n8k16 + cp.async 3-stage --------
// Tile 256(M) x 128(N), BK=32, 512 threads = 16 warps (4x4), warp 64x32.
#define AST_H (256*40)              // halfs per A stage (pitch 40)
#define BST_H (128*40)
#define GEMM_SMEM ((3*AST_H + 3*BST_H)*2)   // 92160 B
__global__ __launch_bounds__(512, 1) void qkv_gemm_h(const float* __restrict__ bias) {
    extern __shared__ __half hs[];
    const uint32_t sb = smem_u32(hs);
    const int tid = threadIdx.x, warp = tid >> 5, lane = tid & 31;
    const int wm = warp >> 2, wn = warp & 3;
    const int g = lane >> 2, c = lane & 3;
    const int bm = blockIdx.y, bn = blockIdx.x;
    const __half* Ab = g_ah + (size_t)bm * 256 * HID_;
    const __half* Wb = g_wh + (size_t)bn * 128 * HID_;

#define GISSUE(st, kt) do {                                                        \
        _Pragma("unroll")                                                          \
        for (int ii = 0; ii < 3; ii++) {                                           \
            int e = tid + ii*512;                                                  \
            if (e < 1024) {                                                        \
                int row = e >> 2, ch = e & 3;                                      \
                cp16(sb + ((st)*AST_H + row*40 + ch*8)*2,                          \
                     Ab + (size_t)row*HID_ + (kt)*32 + ch*8);                      \
            } else {                                                               \
                int e2 = e - 1024;                                                 \
                int row = e2 >> 2, ch = e2 & 3;                                    \
                cp16(sb + (3*AST_H + (st)*BST_H + row*40 + ch*8)*2,                \
                     Wb + (size_t)row*HID_ + (kt)*32 + ch*8);                      \
            }                                                                      \
        }                                                                          \
    } while (0)

    float acc[4][4][4];
#pragma unroll
    for (int i = 0; i < 4; i++)
#pragma unroll
        for (int j = 0; j < 4; j++)
#pragma unroll
            for (int r = 0; r < 4; r++) acc[i][j][r] = 0.0f;

    GISSUE(0, 0); cp_commit();
    GISSUE(1, 1); cp_commit();

    const unsigned* SW = (const unsigned*)hs;
    for (int kt = 0; kt < 32; kt++) {
        if (kt + 1 < 32) cp_wait<1>(); else cp_wait<0>();
        __syncthreads();
        if (kt + 2 < 32) { GISSUE((kt + 2) % 3, kt + 2); cp_commit(); }

        const int abase = (kt % 3) * (AST_H/2);
        const int bbase = 3*(AST_H/2) + (kt % 3) * (BST_H/2);
#pragma unroll
        for (int ks = 0; ks < 2; ks++) {
            unsigned a[4][4], bf[4][2];
#pragma unroll
            for (int i = 0; i < 4; i++) {
                int r = wm*64 + i*16 + g;
                int w0 = abase + r*20 + ks*8 + c;
                a[i][0] = SW[w0];
                a[i][1] = SW[w0 + 160];       // row+8
                a[i][2] = SW[w0 + 4];         // k+8
                a[i][3] = SW[w0 + 164];
            }
#pragma unroll
            for (int j = 0; j < 4; j++) {
                int n = wn*32 + j*8 + g;
                int w0 = bbase + n*20 + ks*8 + c;
                bf[j][0] = SW[w0];
                bf[j][1] = SW[w0 + 4];
            }
#pragma unroll
            for (int i = 0; i < 4; i++)
#pragma unroll
                for (int j = 0; j < 4; j++)
                    mma_f16(acc[i][j], a[i][0], a[i][1], a[i][2], a[i][3],
                            bf[j][0], bf[j][1]);
        }
    }

    // epilogue: bias + scatter (q,k as f32 staging; v as half)
#pragma unroll
    for (int i = 0; i < 4; i++) {
#pragma unroll
        for (int hh = 0; hh < 2; hh++) {
            int m = bm*256 + wm*64 + i*16 + hh*8 + g;
            int bb2 = m >> 11;
            int s  = m & 2047;
#pragma unroll
            for (int j = 0; j < 4; j++) {
                int n = bn*128 + wn*32 + j*8 + 2*c;
                float v0 = acc[i][j][hh*2+0] + bias[n];
                float v1 = acc[i][j][hh*2+1] + bias[n+1];
                if (n < 1024) {
                    float* p = &g_q[((size_t)(bb2*S_+s))*HID_ + n];
                    p[0] = v0; p[1] = v1;
                } else if (n < 2048) {
                    int nn = n - 1024, hd = nn >> 6, dd = nn & 63;
                    float* p = &g_k[(((size_t)(bb2*NH_+hd))*S_ + s)*HD_ + dd];
                    p[0] = v0; p[1] = v1;
                } else {
                    int nn = n - 2048, hd = nn >> 6, dd = nn & 63;
                    *(unsigned*)&g_vh[(((size_t)(bb2*NH_+hd))*S_ + s)*HD_ + dd] = pk(v0, v1);
                }
            }
        }
    }
}

// ---------------- kernel 3: RoPE-K (f32->half) + pool+RoPE-Q (->half) ---------
#define RK_THREADS (B_*NH_*S_*32)
__global__ void ropepool_kernel() {
    int idx = blockIdx.x * blockDim.x + threadIdx.x;
    if (idx < RK_THREADS) {
        int i  = idx & 31;
        int s  = (idx >> 5) & (S_ - 1);
        int bh = idx >> 16;
        float theta = __expf(-(float)i * (9.210340371976184f / 32.0f));
        float ang = (float)s * theta;
        float sn, cs;
        sincosf(ang, &sn, &cs);
        float2 x = ((const float2*)(g_k + ((size_t)bh*S_ + s)*HD_))[i];
        *(unsigned*)&g_kh[((size_t)bh*S_ + s)*HD_ + 2*i] =
            pk(x.x*cs - x.y*sn, x.y*cs + x.x*sn);
    } else {
        int id2 = idx - RK_THREADS;
        int i  = id2 & 31;
        int p  = (id2 >> 5) & (SP_ - 1);
        int bh = id2 >> 15;
        int b = bh >> 4, h = bh & 15;
        int len = g_len[b];
        int s0 = 2 * p;
        int c0 = (s0 < len), c1 = (s0 + 1 < len);
        float norm = (c0 + c1 > 0) ? (float)(c0 + c1) : 1.0f;
        const float2* q0 = (const float2*)(g_q + ((size_t)(b*S_+s0  ))*HID_ + h*HD_) + i;
        const float2* q1 = (const float2*)(g_q + ((size_t)(b*S_+s0+1))*HID_ + h*HD_) + i;
        float2 a = c0 ? *q0 : make_float2(0.f, 0.f);
        float2 c = c1 ? *q1 : make_float2(0.f, 0.f);
        float x0 = (a.x + c.x) / norm;
        float x1 = (a.y + c.y) / norm;
        float theta = __expf(-(float)i * (9.210340371976184f / 32.0f));
        float ang = (float)p * theta;
        float sn, cs;
        sincosf(ang, &sn, &cs);
        *(unsigned*)&g_qh[((size_t)bh*SP_ + p)*HD_ + 2*i] =
            pk((x0*cs - x1*sn)*QSCALE, (x1*cs + x0*sn)*QSCALE);
    }
}

// ---------------- kernel 4: flash attention fp16, P in registers --------------
// grid (8, NH, B), 256 thr = 8 warps; warp = 16 q-rows x full 128 k-cols.
// smem halfs: Q[128][72] @0; K(buf) @9216+buf*18432; V(buf) @+9216.
#define ATTN_SMEM (46080*2)   // 92160 B
__global__ __launch_bounds__(256, 2) void attn_h(float* __restrict__ out) {
    extern __shared__ __half hs[];
    const uint32_t sb = smem_u32(hs);
    const int qt = blockIdx.x, h = blockIdx.y, b = blockIdx.z;
    const int len = g_len[b];
    const int tid = threadIdx.x, warp = tid >> 5, lane = tid & 31;
    const int g = lane >> 2, c = lane & 3;
    const size_t qhb = (size_t)(b*NH_+h)*SP_*HD_;
    const size_t khb = (size_t)(b*NH_+h)*S_*HD_;

    // prologue: Q tile + K/V tile 0 (one cp.async group)
#pragma unroll
    for (int ii = 0; ii < 4; ii++) {
        int e = tid + ii*256;               // 1024 cp16: Q 128 rows x 8 chunks
        int row = e >> 3, ch = e & 7;
        cp16(sb + (row*72 + ch*8)*2, g_qh + qhb + (size_t)(qt*128+row)*HD_ + ch*8);
    }
#define KVLOAD(buf, kt) do {                                                       \
        _Pragma("unroll")                                                          \
        for (int ii = 0; ii < 8; ii++) {                                           \
            int e = tid + ii*256;                                                  \
            if (e < 1024) {                                                        \
                int row = e >> 3, ch = e & 7;                                      \
                cp16(sb + (9216 + (buf)*18432 + row*72 + ch*8)*2,                  \
                     g_kh + khb + (size_t)((kt)*128+row)*HD_ + ch*8);              \
            } else {                                                               \
                int e2 = e - 1024;                                                 \
                int row = e2 >> 3, ch = e2 & 7;                                    \
                cp16(sb + (18432 + (buf)*18432 + row*72 + ch*8)*2,                 \
                     g_vh + khb + (size_t)((kt)*128+row)*HD_ + ch*8);              \
            }                                                                      \
        }                                                                          \
    } while (0)
    KVLOAD(0, 0);
    cp_commit();

    float O[8][4];
    float m0 = -1e30f, m1 = -1e30f, l0 = 0.0f, l1 = 0.0f;
#pragma unroll
    for (int nt = 0; nt < 8; nt++)
#pragma unroll
        for (int r = 0; r < 4; r++) O[nt][r] = 0.0f;

    const unsigned* SW = (const unsigned*)hs;
    const int ntiles = (len + 127) >> 7;
    int buf = 0;

    for (int kt = 0; kt < ntiles; kt++) {
        if (kt + 1 < ntiles) { KVLOAD(buf ^ 1, kt + 1); cp_commit(); cp_wait<1>(); }
        else cp_wait<0>();
        __syncthreads();

        // ---- S = Q K^T ----
        float s[16][4];
#pragma unroll
        for (int nt = 0; nt < 16; nt++)
#pragma unroll
            for (int r = 0; r < 4; r++) s[nt][r] = 0.0f;

        const int kbw = (9216 + buf*18432) >> 1;       // word base of K
#pragma unroll
        for (int ks = 0; ks < 4; ks++) {
            int qw = (warp*16 + g)*36 + ks*8 + c;
            unsigned a0 = SW[qw], a1 = SW[qw + 288], a2 = SW[qw + 4], a3 = SW[qw + 292];
#pragma unroll
            for (int nt = 0; nt < 16; nt++) {
                int kw = kbw + (nt*8 + g)*36 + ks*8 + c;
                mma_f16(s[nt], a0, a1, a2, a3, SW[kw], SW[kw + 4]);
            }
        }

        // ---- mask partial tile ----
        if (kt == ntiles - 1 && (len & 127)) {
#pragma unroll
            for (int nt = 0; nt < 16; nt++)
#pragma unroll
                for (int cc = 0; cc < 2; cc++) {
                    int kcol = kt*128 + nt*8 + 2*c + cc;
                    if (kcol >= len) { s[nt][cc] = -1e30f; s[nt][2+cc] = -1e30f; }
                }
        }

        // ---- warp-local online softmax (exp2 domain) ----
        float mx0 = s[0][0], mx1 = s[0][2];
#pragma unroll
        for (int nt = 0; nt < 16; nt++) {
            mx0 = fmaxf(mx0, fmaxf(s[nt][0], s[nt][1]));
            mx1 = fmaxf(mx1, fmaxf(s[nt][2], s[nt][3]));
        }
        mx0 = fmaxf(mx0, __shfl_xor_sync(0xffffffffu, mx0, 1));
        mx0 = fmaxf(mx0, __shfl_xor_sync(0xffffffffu, mx0, 2));
        mx1 = fmaxf(mx1, __shfl_xor_sync(0xffffffffu, mx1, 1));
        mx1 = fmaxf(mx1, __shfl_xor_sync(0xffffffffu, mx1, 2));
        float mn0 = fmaxf(m0, mx0), mn1 = fmaxf(m1, mx1);
        float cr0 = exp2f(m0 - mn0), cr1 = exp2f(m1 - mn1);
        m0 = mn0; m1 = mn1;
        float r0 = 0.0f, r1 = 0.0f;
#pragma unroll
        for (int nt = 0; nt < 16; nt++) {
            float e0 = exp2f(s[nt][0] - mn0);
            float e1 = exp2f(s[nt][1] - mn0);
            float e2 = exp2f(s[nt][2] - mn1);
            float e3 = exp2f(s[nt][3] - mn1);
            s[nt][0] = e0; s[nt][1] = e1; s[nt][2] = e2; s[nt][3] = e3;
            r0 += e0 + e1; r1 += e2 + e3;
        }
        r0 += __shfl_xor_sync(0xffffffffu, r0, 1);
        r0 += __shfl_xor_sync(0xffffffffu, r0, 2);
        r1 += __shfl_xor_sync(0xffffffffu, r1, 1);
        r1 += __shfl_xor_sync(0xffffffffu, r1, 2);
        l0 = l0*cr0 + r0; l1 = l1*cr1 + r1;
#pragma unroll
        for (int nt = 0; nt < 8; nt++) {
            O[nt][0] *= cr0; O[nt][1] *= cr0;
            O[nt][2] *= cr1; O[nt][3] *= cr1;
        }

        // ---- O += P V (P packed from registers; V via ldmatrix.trans) ----
        const uint32_t vlb = sb + (18432 + buf*18432)*2 + (lane & 15)*144;
#pragma unroll
        for (int pkt = 0; pkt < 8; pkt++) {
            unsigned a0 = pk(s[2*pkt][0],   s[2*pkt][1]);
            unsigned a1 = pk(s[2*pkt][2],   s[2*pkt][3]);
            unsigned a2 = pk(s[2*pkt+1][0], s[2*pkt+1][1]);
            unsigned a3 = pk(s[2*pkt+1][2], s[2*pkt+1][3]);
#pragma unroll
            for (int nt = 0; nt < 8; nt++) {
                unsigned b0, b1;
                ldsm2t(b0, b1, vlb + pkt*2304 + nt*16);
                mma_f16(O[nt], a0, a1, a2, a3, b0, b1);
            }
        }
        __syncthreads();
        buf ^= 1;
    }

    // ---- epilogue ----
    int q0r = qt*128 + warp*16 + g;
    int q1r = q0r + 8;
    float inv0 = (2*q0r < len) ? (1.0f / l0) : 0.0f;
    float inv1 = (2*q1r < len) ? (1.0f / l1) : 0.0f;
#pragma unroll
    for (int nt = 0; nt < 8; nt++) {
        int col = h*HD_ + nt*8 + 2*c;
        *(float2*)&out[((size_t)(b*SP_ + q0r))*(NH_*HD_) + col] =
            make_float2(O[nt][0]*inv0, O[nt][1]*inv0);
        *(float2*)&out[((size_t)(b*SP_ + q1r))*(NH_*HD_) + col] =
            make_float2(O[nt][2]*inv1, O[nt][3]*inv1);
    }
}

// ---------------- launcher ----------------------------------------------------
extern "C" void kernel_launch(void* const* d_in, const int* in_sizes, int n_in,
                              void* d_out, int out_size) {
    const float* hidden = (const float*)d_in[0];
    const void*  mask   = d_in[1];
    const float* W      = (const float*)d_in[2];
    const float* bias   = (const float*)d_in[3];
    float* out = (float*)d_out;

    cvtlen_kernel<<<(A4_ + W4_) / 256, 256>>>(hidden, W, mask);

    cudaFuncSetAttribute(qkv_gemm_h, cudaFuncAttributeMaxDynamicSharedMemorySize, GEMM_SMEM);
    dim3 gg(NQKV_/128, (B_*S_)/256);   // (24, 64)
    qkv_gemm_h<<<gg, 512, GEMM_SMEM>>>(bias);

    ropepool_kernel<<<(RK_THREADS + B_*NH_*SP_*32) / 256, 256>>>();

    cudaFuncSetAttribute(attn_h, cudaFuncAttributeMaxDynamicSharedMemorySize, ATTN_SMEM);
    dim3 ga(SP_/128, NH_, B_);
    attn_h<<<ga, 256, ATTN_SMEM>>>(out);
}

// round 8
// speedup vs baseline: 2.5103x; 1.0991x over previous
#include <cuda_runtime.h>
#include <cuda_fp16.h>
#include <cstdint>
#include <math.h>

#define B_    8
#define S_    2048
#define HID_  1024
#define NH_   16
#define HD_   64
#define SP_   1024
#define NQKV_ 3072
#define QSCALE 0.18033688f   // 0.125 * log2(e)

// ---------------- scratch ----------------------------------------------------
__device__ __half g_ah[B_*S_*HID_];       // half hidden
__device__ __half g_wh[NQKV_*HID_];       // half Wqkv
__device__ float  g_q [B_*S_*HID_];       // q pre-pool f32
__device__ __half g_kh[B_*NH_*S_*HD_];    // roped K half
__device__ __half g_vh[B_*NH_*S_*HD_];    // V half
__device__ __half g_qh[B_*NH_*SP_*HD_];   // pooled+roped+scaled Q half
__device__ int    g_len[B_];

// ---------------- helpers -----------------------------------------------------
__device__ __forceinline__ void mma_f16(float* d,
        unsigned a0, unsigned a1, unsigned a2, unsigned a3,
        unsigned b0, unsigned b1) {
    asm volatile("mma.sync.aligned.m16n8k16.row.col.f32.f16.f16.f32 "
        "{%0,%1,%2,%3},{%4,%5,%6,%7},{%8,%9},{%0,%1,%2,%3};\n"
        : "+f"(d[0]), "+f"(d[1]), "+f"(d[2]), "+f"(d[3])
        : "r"(a0), "r"(a1), "r"(a2), "r"(a3), "r"(b0), "r"(b1));
}
__device__ __forceinline__ unsigned pk(float lo, float hi) {
    __half2 h = __floats2half2_rn(lo, hi);
    return *reinterpret_cast<unsigned*>(&h);
}
__device__ __forceinline__ unsigned ex2h2(unsigned x) {
    unsigned r; asm("ex2.approx.f16x2 %0, %1;" : "=r"(r) : "r"(x)); return r;
}
__device__ __forceinline__ uint32_t smem_u32(const void* p) {
    uint32_t a;
    asm("{ .reg .u64 t; cvta.to.shared.u64 t, %1; cvt.u32.u64 %0, t; }"
        : "=r"(a) : "l"(p));
    return a;
}
__device__ __forceinline__ void cp16(uint32_t saddr, const void* gptr) {
    asm volatile("cp.async.cg.shared.global [%0], [%1], 16;"
                 :: "r"(saddr), "l"(gptr));
}
__device__ __forceinline__ void cp_commit() { asm volatile("cp.async.commit_group;"); }
template <int N>
__device__ __forceinline__ void cp_wait() {
    asm volatile("cp.async.wait_group %0;" :: "n"(N));
}
__device__ __forceinline__ void ldsm4(unsigned& r0, unsigned& r1, unsigned& r2,
                                      unsigned& r3, uint32_t addr) {
    asm volatile("ldmatrix.sync.aligned.m8n8.x4.shared.b16 {%0,%1,%2,%3}, [%4];"
        : "=r"(r0), "=r"(r1), "=r"(r2), "=r"(r3) : "r"(addr));
}
__device__ __forceinline__ void ldsm4t(unsigned& r0, unsigned& r1, unsigned& r2,
                                       unsigned& r3, uint32_t addr) {
    asm volatile("ldmatrix.sync.aligned.m8n8.x4.trans.shared.b16 {%0,%1,%2,%3}, [%4];"
        : "=r"(r0), "=r"(r1), "=r"(r2), "=r"(r3) : "r"(addr));
}

// ---------------- kernel 1: half pre-convert of A & W, plus lengths -----------
#define A4_ (B_*S_*HID_/4)
#define W4_ (NQKV_*HID_/4)
__global__ void cvtlen_kernel(const float* __restrict__ hidden,
                              const float* __restrict__ W,
                              const void*  __restrict__ mask) {
    int i = blockIdx.x * 256 + threadIdx.x;
    if (i < A4_) {
        float4 v = ((const float4*)hidden)[i];
        ((uint2*)g_ah)[i] = make_uint2(pk(v.x, v.y), pk(v.z, v.w));
    } else {
        int j = i - A4_;
        if (j < W4_) {
            float4 v = ((const float4*)W)[j];
            ((uint2*)g_wh)[j] = make_uint2(pk(v.x, v.y), pk(v.z, v.w));
        }
    }
    if (blockIdx.x == 0) {
        __shared__ int sred[256];
        const int* mi = (const int*)mask;
        int w = mi[16];
        int mode = (w == 1) ? 0 : ((w == 0x3F800000) ? 1 : 2);
        for (int b = 0; b < B_; b++) {
            int cnt = 0;
            for (int s = threadIdx.x; s < S_; s += 256) {
                int v;
                if (mode == 0)      v = (mi[b*S_+s] != 0);
                else if (mode == 1) v = (((const float*)mask)[b*S_+s] != 0.0f);
                else                v = (((const unsigned char*)mask)[b*S_+s] != 0);
                cnt += v;
            }
            sred[threadIdx.x] = cnt;
            __syncthreads();
            for (int st = 128; st > 0; st >>= 1) {
                if (threadIdx.x < st) sred[threadIdx.x] += sred[threadIdx.x + st];
                __syncthreads();
            }
            if (threadIdx.x == 0) g_len[b] = sred[0];
            __syncthreads();
        }
    }
}

// ---------------- kernel 2: QKV GEMM fp16, ldmatrix frags, fused RoPE-K -------
// Tile 256(M) x 128(N), BK=32, 512 threads = 16 warps (4x4), warp 64x32.
#define AST_H (256*40)
#define BST_H (128*40)
#define GEMM_SMEM ((3*AST_H + 3*BST_H)*2)   // 92160 B
__global__ __launch_bounds__(512, 1) void qkv_gemm_h(const float* __restrict__ bias) {
    extern __shared__ __half hs[];
    const uint32_t sb = smem_u32(hs);
    const int tid = threadIdx.x, warp = tid >> 5, lane = tid & 31;
    const int wm = warp >> 2, wn = warp & 3;
    const int g = lane >> 2, c = lane & 3;
    const int bm = blockIdx.y, bn = blockIdx.x;
    const __half* Ab = g_ah + (size_t)bm * 256 * HID_;
    const __half* Wb = g_wh + (size_t)bn * 128 * HID_;

#define GISSUE(st, kt) do {                                                        \
        _Pragma("unroll")                                                          \
        for (int ii = 0; ii < 3; ii++) {                                           \
            int e = tid + ii*512;                                                  \
            if (e < 1024) {                                                        \
                int row = e >> 2, ch = e & 3;                                      \
                cp16(sb + ((st)*AST_H + row*40 + ch*8)*2,                          \
                     Ab + (size_t)row*HID_ + (kt)*32 + ch*8);                      \
            } else {                                                               \
                int e2 = e - 1024;                                                 \
                int row = e2 >> 2, ch = e2 & 3;                                    \
                cp16(sb + (3*AST_H + (st)*BST_H + row*40 + ch*8)*2,                \
                     Wb + (size_t)row*HID_ + (kt)*32 + ch*8);                      \
            }                                                                      \
        }                                                                          \
    } while (0)

    float acc[4][4][4];
#pragma unroll
    for (int i = 0; i < 4; i++)
#pragma unroll
        for (int j = 0; j < 4; j++)
#pragma unroll
            for (int r = 0; r < 4; r++) acc[i][j][r] = 0.0f;

    GISSUE(0, 0); cp_commit();
    GISSUE(1, 1); cp_commit();

    const int l8  = ((lane >> 3) & 1) * 8;
    const int l16 = ((lane >> 4) & 1) * 8;
    for (int kt = 0; kt < 32; kt++) {
        if (kt + 1 < 32) cp_wait<1>(); else cp_wait<0>();
        __syncthreads();
        if (kt + 2 < 32) { GISSUE((kt + 2) % 3, kt + 2); cp_commit(); }

        const uint32_t abase = sb + ((kt % 3) * AST_H) * 2;
        const uint32_t bbase = sb + (3*AST_H + (kt % 3) * BST_H) * 2;
#pragma unroll
        for (int ks = 0; ks < 2; ks++) {
            unsigned a[4][4], bf[4][2];
#pragma unroll
            for (int i = 0; i < 4; i++) {
                uint32_t ad = abase +
                    ((wm*64 + i*16 + (lane&7) + l8)*40 + ks*16 + l16)*2;
                ldsm4(a[i][0], a[i][1], a[i][2], a[i][3], ad);
            }
#pragma unroll
            for (int jp = 0; jp < 2; jp++) {
                uint32_t bd = bbase +
                    ((wn*32 + jp*16 + (lane&7) + l16)*40 + ks*16 + l8)*2;
                ldsm4(bf[2*jp][0], bf[2*jp][1], bf[2*jp+1][0], bf[2*jp+1][1], bd);
            }
#pragma unroll
            for (int i = 0; i < 4; i++)
#pragma unroll
                for (int j = 0; j < 4; j++)
                    mma_f16(acc[i][j], a[i][0], a[i][1], a[i][2], a[i][3],
                            bf[j][0], bf[j][1]);
        }
    }

    // epilogue: bias; q -> f32 staging; K -> RoPE -> half; V -> half
#pragma unroll
    for (int i = 0; i < 4; i++) {
#pragma unroll
        for (int hh = 0; hh < 2; hh++) {
            int m = bm*256 + wm*64 + i*16 + hh*8 + g;
            int bb2 = m >> 11;
            int sq = m & 2047;
#pragma unroll
            for (int j = 0; j < 4; j++) {
                int n = bn*128 + wn*32 + j*8 + 2*c;
                float v0 = acc[i][j][hh*2+0] + bias[n];
                float v1 = acc[i][j][hh*2+1] + bias[n+1];
                if (n < 1024) {
                    float* p = &g_q[((size_t)(bb2*S_+sq))*HID_ + n];
                    p[0] = v0; p[1] = v1;
                } else if (n < 2048) {
                    int nn = n - 1024, hd = nn >> 6, dd = nn & 63;
                    int ir = dd >> 1;
                    float theta = __expf(-(float)ir * (9.210340371976184f / 32.0f));
                    float sn, cs;
                    sincosf((float)sq * theta, &sn, &cs);
                    *(unsigned*)&g_kh[(((size_t)(bb2*NH_+hd))*S_ + sq)*HD_ + dd] =
                        pk(v0*cs - v1*sn, v1*cs + v0*sn);
                } else {
                    int nn = n - 2048, hd = nn >> 6, dd = nn & 63;
                    *(unsigned*)&g_vh[(((size_t)(bb2*NH_+hd))*S_ + sq)*HD_ + dd] = pk(v0, v1);
                }
            }
        }
    }
}

// ---------------- kernel 3: pool+RoPE-Q (->half, pre-scaled) ------------------
__global__ void ropeq_kernel() {
    int idx = blockIdx.x * blockDim.x + threadIdx.x;   // B*NH*SP*32 threads
    int i  = idx & 31;
    int p  = (idx >> 5) & (SP_ - 1);
    int bh = idx >> 15;
    int b = bh >> 4, h = bh & 15;
    int len = g_len[b];
    int s0 = 2 * p;
    int c0 = (s0 < len), c1 = (s0 + 1 < len);
    float norm = (c0 + c1 > 0) ? (float)(c0 + c1) : 1.0f;
    const float2* q0 = (const float2*)(g_q + ((size_t)(b*S_+s0  ))*HID_ + h*HD_) + i;
    const float2* q1 = (const float2*)(g_q + ((size_t)(b*S_+s0+1))*HID_ + h*HD_) + i;
    float2 a = c0 ? *q0 : make_float2(0.f, 0.f);
    float2 c = c1 ? *q1 : make_float2(0.f, 0.f);
    float x0 = (a.x + c.x) / norm;
    float x1 = (a.y + c.y) / norm;
    float theta = __expf(-(float)i * (9.210340371976184f / 32.0f));
    float ang = (float)p * theta;
    float sn, cs;
    sincosf(ang, &sn, &cs);
    *(unsigned*)&g_qh[((size_t)bh*SP_ + p)*HD_ + 2*i] =
        pk((x0*cs - x1*sn)*QSCALE, (x1*cs + x0*sn)*QSCALE);
}

// ---------------- kernel 4: flash attention fp16, ldmatrix + tensor-sum -------
// grid (8, NH, B), 256 thr = 8 warps; warp = 16 q-rows x 128 k-cols.
// smem halfs: Q[128][72] @0; K(buf) @9216+buf*18432; V(buf) @18432+buf*18432.
// V pad cols 64-71 hold 1.0h -> PV n-tile 8 accumulates row sums (= l).
#define ATTN_SMEM (46080*2)   // 92160 B
__global__ __launch_bounds__(256, 2) void attn_h(float* __restrict__ out) {
    extern __shared__ __half hs[];
    const uint32_t sb = smem_u32(hs);
    const int qt = blockIdx.x, h = blockIdx.y, b = blockIdx.z;
    const int len = g_len[b];
    const int tid = threadIdx.x, warp = tid >> 5, lane = tid & 31;
    const int g = lane >> 2, c = lane & 3;
    const int l8  = ((lane >> 3) & 1) * 8;
    const int l16 = ((lane >> 4) & 1) * 8;
    const size_t qhb = (size_t)(b*NH_+h)*SP_*HD_;
    const size_t khb = (size_t)(b*NH_+h)*S_*HD_;

    // Q tile (cp.async) + ones-pads for both V buffers
#pragma unroll
    for (int ii = 0; ii < 4; ii++) {
        int e = tid + ii*256;
        int row = e >> 3, ch = e & 7;
        cp16(sb + (row*72 + ch*8)*2, g_qh + qhb + (size_t)(qt*128+row)*HD_ + ch*8);
    }
#pragma unroll
    for (int ii = 0; ii < 4; ii++) {
        int e = tid + ii*256;                  // 1024 words: 2 bufs x 128 rows x 4
        int bf = e >> 9, row = (e >> 2) & 127, u = e & 3;
        *(unsigned*)&hs[18432 + bf*18432 + row*72 + 64 + u*2] = 0x3C003C00u;
    }
#define KVLOAD(buf, kt) do {                                                       \
        _Pragma("unroll")                                                          \
        for (int ii = 0; ii < 8; ii++) {                                           \
            int e = tid + ii*256;                                                  \
            if (e < 1024) {                                                        \
                int row = e >> 3, ch = e & 7;                                      \
                cp16(sb + (9216 + (buf)*18432 + row*72 + ch*8)*2,                  \
                     g_kh + khb + (size_t)((kt)*128+row)*HD_ + ch*8);              \
            } else {                                                               \
                int e2 = e - 1024;                                                 \
                int row = e2 >> 3, ch = e2 & 7;                                    \
                cp16(sb + (18432 + (buf)*18432 + row*72 + ch*8)*2,                 \
                     g_vh + khb + (size_t)((kt)*128+row)*HD_ + ch*8);              \
            }                                                                      \
        }                                                                          \
    } while (0)
    KVLOAD(0, 0);
    cp_commit();

    float O[9][4];
    float m0 = -1e30f, m1 = -1e30f;
#pragma unroll
    for (int nt = 0; nt < 9; nt++)
#pragma unroll
        for (int r = 0; r < 4; r++) O[nt][r] = 0.0f;

    const int ntiles = (len + 127) >> 7;
    int buf = 0;

    for (int kt = 0; kt < ntiles; kt++) {
        if (kt + 1 < ntiles) { KVLOAD(buf ^ 1, kt + 1); cp_commit(); cp_wait<1>(); }
        else cp_wait<0>();
        __syncthreads();

        // ---- S = Q K^T  (all frags via ldmatrix.x4) ----
        float s[16][4];
#pragma unroll
        for (int nt = 0; nt < 16; nt++)
#pragma unroll
            for (int r = 0; r < 4; r++) s[nt][r] = 0.0f;

        const int kH = 9216 + buf*18432;
#pragma unroll
        for (int ks = 0; ks < 4; ks++) {
            uint32_t ad = sb + ((warp*16 + (lane&7) + l8)*72 + ks*16 + l16)*2;
            unsigned a0, a1, a2, a3;
            ldsm4(a0, a1, a2, a3, ad);
#pragma unroll
            for (int ntp = 0; ntp < 8; ntp++) {
                uint32_t bd = sb + (kH + (ntp*16 + (lane&7) + l16)*72 + ks*16 + l8)*2;
                unsigned b0, b1, b2, b3;
                ldsm4(b0, b1, b2, b3, bd);
                mma_f16(s[2*ntp],   a0, a1, a2, a3, b0, b1);
                mma_f16(s[2*ntp+1], a0, a1, a2, a3, b2, b3);
            }
        }

        // ---- mask partial tile ----
        if (kt == ntiles - 1 && (len & 127)) {
#pragma unroll
            for (int nt = 0; nt < 16; nt++)
#pragma unroll
                for (int cc = 0; cc < 2; cc++) {
                    int kcol = kt*128 + nt*8 + 2*c + cc;
                    if (kcol >= len) { s[nt][cc] = -1e30f; s[nt][2+cc] = -1e30f; }
                }
        }

        // ---- online max + corr ----
        float mx0 = -1e30f, mx1 = -1e30f;
#pragma unroll
        for (int nt = 0; nt < 16; nt++) {
            mx0 = fmaxf(mx0, fmaxf(s[nt][0], s[nt][1]));
            mx1 = fmaxf(mx1, fmaxf(s[nt][2], s[nt][3]));
        }
        mx0 = fmaxf(mx0, __shfl_xor_sync(0xffffffffu, mx0, 1));
        mx0 = fmaxf(mx0, __shfl_xor_sync(0xffffffffu, mx0, 2));
        mx1 = fmaxf(mx1, __shfl_xor_sync(0xffffffffu, mx1, 1));
        mx1 = fmaxf(mx1, __shfl_xor_sync(0xffffffffu, mx1, 2));
        float mn0 = fmaxf(m0, mx0), mn1 = fmaxf(m1, mx1);
        float cr0 = exp2f(m0 - mn0), cr1 = exp2f(m1 - mn1);
        m0 = mn0; m1 = mn1;

        // ---- exp in fp16x2 (packed = PV a-frags) ----
        unsigned ph[16][2];
#pragma unroll
        for (int nt = 0; nt < 16; nt++) {
            ph[nt][0] = ex2h2(pk(s[nt][0] - mn0, s[nt][1] - mn0));
            ph[nt][1] = ex2h2(pk(s[nt][2] - mn1, s[nt][3] - mn1));
        }
#pragma unroll
        for (int nt = 0; nt < 9; nt++) {
            O[nt][0] *= cr0; O[nt][1] *= cr0;
            O[nt][2] *= cr1; O[nt][3] *= cr1;
        }

        // ---- O += P V  (V + ones column via ldmatrix.x4.trans) ----
        const int vH = 18432 + buf*18432;
#pragma unroll
        for (int t = 0; t < 4; t++) {
            unsigned pa0 = ph[4*t][0],   pa1 = ph[4*t][1];
            unsigned pa2 = ph[4*t+1][0], pa3 = ph[4*t+1][1];
            unsigned qa0 = ph[4*t+2][0], qa1 = ph[4*t+2][1];
            unsigned qa2 = ph[4*t+3][0], qa3 = ph[4*t+3][1];
#pragma unroll
            for (int nt = 0; nt < 9; nt++) {
                uint32_t vd = sb + (vH + (t*32 + lane)*72 + nt*8)*2;
                unsigned b0, b1, b2, b3;
                ldsm4t(b0, b1, b2, b3, vd);
                mma_f16(O[nt], pa0, pa1, pa2, pa3, b0, b1);
                mma_f16(O[nt], qa0, qa1, qa2, qa3, b2, b3);
            }
        }
        __syncthreads();
        buf ^= 1;
    }

    // ---- epilogue: l = O[8]; 1/l; q_mask; write ----
    int q0r = qt*128 + warp*16 + g;
    int q1r = q0r + 8;
    float inv0 = (2*q0r < len) ? (1.0f / O[8][0]) : 0.0f;
    float inv1 = (2*q1r < len) ? (1.0f / O[8][2]) : 0.0f;
#pragma unroll
    for (int nt = 0; nt < 8; nt++) {
        int col = h*HD_ + nt*8 + 2*c;
        *(float2*)&out[((size_t)(b*SP_ + q0r))*(NH_*HD_) + col] =
            make_float2(O[nt][0]*inv0, O[nt][1]*inv0);
        *(float2*)&out[((size_t)(b*SP_ + q1r))*(NH_*HD_) + col] =
            make_float2(O[nt][2]*inv1, O[nt][3]*inv1);
    }
}

// ---------------- launcher ----------------------------------------------------
extern "C" void kernel_launch(void* const* d_in, const int* in_sizes, int n_in,
                              void* d_out, int out_size) {
    const float* hidden = (const float*)d_in[0];
    const void*  mask   = d_in[1];
    const float* W      = (const float*)d_in[2];
    const float* bias   = (const float*)d_in[3];
    float* out = (float*)d_out;

    cvtlen_kernel<<<(A4_ + W4_) / 256, 256>>>(hidden, W, mask);

    cudaFuncSetAttribute(qkv_gemm_h, cudaFuncAttributeMaxDynamicSharedMemorySize, GEMM_SMEM);
    dim3 gg(NQKV_/128, (B_*S_)/256);   // (24, 64)
    qkv_gemm_h<<<gg, 512, GEMM_SMEM>>>(bias);

    ropeq_kernel<<<(B_*NH_*SP_*32) / 256, 256>>>();

    cudaFuncSetAttribute(attn_h, cudaFuncAttributeMaxDynamicSharedMemorySize, ATTN_SMEM);
    dim3 ga(SP_/128, NH_, B_);
    attn_h<<<ga, 256, ATTN_SMEM>>>(out);
}

// round 9
// speedup vs baseline: 2.8530x; 1.1365x over previous
#include <cuda_runtime.h>
#include <cuda_fp16.h>
#include <cstdint>
#include <math.h>

#define B_    8
#define S_    2048
#define HID_  1024
#define NH_   16
#define HD_   64
#define SP_   1024
#define NQKV_ 3072
#define QSCALE 0.18033688f   // 0.125 * log2(e)

// ---------------- scratch ----------------------------------------------------
__device__ __half g_ah[B_*S_*HID_];       // half hidden
__device__ __half g_wh[NQKV_*HID_];       // half Wqkv
__device__ float  g_q [B_*S_*HID_];       // q pre-pool f32
__device__ __half g_kh[B_*NH_*S_*HD_];    // roped K half
__device__ __half g_vh[B_*NH_*S_*HD_];    // V half
__device__ __half g_qh[B_*NH_*SP_*HD_];   // pooled+roped+scaled Q half
__device__ int    g_len[B_];

// ---------------- helpers -----------------------------------------------------
__device__ __forceinline__ void mma_f16(float* d,
        unsigned a0, unsigned a1, unsigned a2, unsigned a3,
        unsigned b0, unsigned b1) {
    asm volatile("mma.sync.aligned.m16n8k16.row.col.f32.f16.f16.f32 "
        "{%0,%1,%2,%3},{%4,%5,%6,%7},{%8,%9},{%0,%1,%2,%3};\n"
        : "+f"(d[0]), "+f"(d[1]), "+f"(d[2]), "+f"(d[3])
        : "r"(a0), "r"(a1), "r"(a2), "r"(a3), "r"(b0), "r"(b1));
}
__device__ __forceinline__ unsigned pk(float lo, float hi) {
    __half2 h = __floats2half2_rn(lo, hi);
    return *reinterpret_cast<unsigned*>(&h);
}
__device__ __forceinline__ unsigned ex2h2(unsigned x) {
    unsigned r; asm("ex2.approx.f16x2 %0, %1;" : "=r"(r) : "r"(x)); return r;
}
__device__ __forceinline__ uint32_t smem_u32(const void* p) {
    uint32_t a;
    asm("{ .reg .u64 t; cvta.to.shared.u64 t, %1; cvt.u32.u64 %0, t; }"
        : "=r"(a) : "l"(p));
    return a;
}
__device__ __forceinline__ void cp16(uint32_t saddr, const void* gptr) {
    asm volatile("cp.async.cg.shared.global [%0], [%1], 16;"
                 :: "r"(saddr), "l"(gptr));
}
__device__ __forceinline__ void cp_commit() { asm volatile("cp.async.commit_group;"); }
template <int N>
__device__ __forceinline__ void cp_wait() {
    asm volatile("cp.async.wait_group %0;" :: "n"(N));
}
__device__ __forceinline__ void ldsm4(unsigned& r0, unsigned& r1, unsigned& r2,
                                      unsigned& r3, uint32_t addr) {
    asm volatile("ldmatrix.sync.aligned.m8n8.x4.shared.b16 {%0,%1,%2,%3}, [%4];"
        : "=r"(r0), "=r"(r1), "=r"(r2), "=r"(r3) : "r"(addr));
}
__device__ __forceinline__ void ldsm4t(unsigned& r0, unsigned& r1, unsigned& r2,
                                       unsigned& r3, uint32_t addr) {
    asm volatile("ldmatrix.sync.aligned.m8n8.x4.trans.shared.b16 {%0,%1,%2,%3}, [%4];"
        : "=r"(r0), "=r"(r1), "=r"(r2), "=r"(r3) : "r"(addr));
}

// ---------------- kernel 1: half pre-convert of A & W, plus lengths -----------
#define A4_ (B_*S_*HID_/4)
#define W4_ (NQKV_*HID_/4)
__global__ void cvtlen_kernel(const float* __restrict__ hidden,
                              const float* __restrict__ W,
                              const void*  __restrict__ mask) {
    int i = blockIdx.x * 256 + threadIdx.x;
    if (i < A4_) {
        float4 v = ((const float4*)hidden)[i];
        ((uint2*)g_ah)[i] = make_uint2(pk(v.x, v.y), pk(v.z, v.w));
    } else {
        int j = i - A4_;
        if (j < W4_) {
            float4 v = ((const float4*)W)[j];
            ((uint2*)g_wh)[j] = make_uint2(pk(v.x, v.y), pk(v.z, v.w));
        }
    }
    if (blockIdx.x == 0) {
        __shared__ int sred[256];
        const int* mi = (const int*)mask;
        int w = mi[16];
        int mode = (w == 1) ? 0 : ((w == 0x3F800000) ? 1 : 2);
        for (int b = 0; b < B_; b++) {
            int cnt = 0;
            for (int s = threadIdx.x; s < S_; s += 256) {
                int v;
                if (mode == 0)      v = (mi[b*S_+s] != 0);
                else if (mode == 1) v = (((const float*)mask)[b*S_+s] != 0.0f);
                else                v = (((const unsigned char*)mask)[b*S_+s] != 0);
                cnt += v;
            }
            sred[threadIdx.x] = cnt;
            __syncthreads();
            for (int st = 128; st > 0; st >>= 1) {
                if (threadIdx.x < st) sred[threadIdx.x] += sred[threadIdx.x + st];
                __syncthreads();
            }
            if (threadIdx.x == 0) g_len[b] = sred[0];
            __syncthreads();
        }
    }
}

// ---------------- kernel 2: QKV GEMM fp16, 128x128 tile, 2 CTAs/SM ------------
// BK=32, 3-stage cp.async, 256 threads = 8 warps (2x4), warp 64x32.
#define AST_H (128*40)
#define BST_H (128*40)
#define GEMM_SMEM ((3*AST_H + 3*BST_H)*2)   // 61440 B
__global__ __launch_bounds__(256, 2) void qkv_gemm_h(const float* __restrict__ bias) {
    extern __shared__ __half hs[];
    const uint32_t sb = smem_u32(hs);
    const int tid = threadIdx.x, warp = tid >> 5, lane = tid & 31;
    const int wm = warp >> 2, wn = warp & 3;
    const int g = lane >> 2, c = lane & 3;
    const int bm = blockIdx.y, bn = blockIdx.x;
    const __half* Ab = g_ah + (size_t)bm * 128 * HID_;
    const __half* Wb = g_wh + (size_t)bn * 128 * HID_;

#define GISSUE(st, kt) do {                                                        \
        _Pragma("unroll")                                                          \
        for (int ii = 0; ii < 4; ii++) {                                           \
            int e = tid + ii*256;                                                  \
            if (e < 512) {                                                         \
                int row = e >> 2, ch = e & 3;                                      \
                cp16(sb + ((st)*AST_H + row*40 + ch*8)*2,                          \
                     Ab + (size_t)row*HID_ + (kt)*32 + ch*8);                      \
            } else {                                                               \
                int e2 = e - 512;                                                  \
                int row = e2 >> 2, ch = e2 & 3;                                    \
                cp16(sb + (3*AST_H + (st)*BST_H + row*40 + ch*8)*2,                \
                     Wb + (size_t)row*HID_ + (kt)*32 + ch*8);                      \
            }                                                                      \
        }                                                                          \
    } while (0)

    float acc[4][4][4];
#pragma unroll
    for (int i = 0; i < 4; i++)
#pragma unroll
        for (int j = 0; j < 4; j++)
#pragma unroll
            for (int r = 0; r < 4; r++) acc[i][j][r] = 0.0f;

    GISSUE(0, 0); cp_commit();
    GISSUE(1, 1); cp_commit();

    const int l8  = ((lane >> 3) & 1) * 8;
    const int l16 = ((lane >> 4) & 1) * 8;
    for (int kt = 0; kt < 32; kt++) {
        if (kt + 1 < 32) cp_wait<1>(); else cp_wait<0>();
        __syncthreads();
        if (kt + 2 < 32) { GISSUE((kt + 2) % 3, kt + 2); cp_commit(); }

        const uint32_t abase = sb + ((kt % 3) * AST_H) * 2;
        const uint32_t bbase = sb + (3*AST_H + (kt % 3) * BST_H) * 2;
#pragma unroll
        for (int ks = 0; ks < 2; ks++) {
            unsigned a[4][4], bf[4][2];
#pragma unroll
            for (int i = 0; i < 4; i++) {
                uint32_t ad = abase +
                    ((wm*64 + i*16 + (lane&7) + l8)*40 + ks*16 + l16)*2;
                ldsm4(a[i][0], a[i][1], a[i][2], a[i][3], ad);
            }
#pragma unroll
            for (int jp = 0; jp < 2; jp++) {
                uint32_t bd = bbase +
                    ((wn*32 + jp*16 + (lane&7) + l16)*40 + ks*16 + l8)*2;
                ldsm4(bf[2*jp][0], bf[2*jp][1], bf[2*jp+1][0], bf[2*jp+1][1], bd);
            }
#pragma unroll
            for (int i = 0; i < 4; i++)
#pragma unroll
                for (int j = 0; j < 4; j++)
                    mma_f16(acc[i][j], a[i][0], a[i][1], a[i][2], a[i][3],
                            bf[j][0], bf[j][1]);
        }
    }

    // epilogue: bias; q -> f32 staging; K -> RoPE -> half; V -> half
#pragma unroll
    for (int i = 0; i < 4; i++) {
#pragma unroll
        for (int hh = 0; hh < 2; hh++) {
            int m = bm*128 + wm*64 + i*16 + hh*8 + g;
            int bb2 = m >> 11;
            int sq = m & 2047;
#pragma unroll
            for (int j = 0; j < 4; j++) {
                int n = bn*128 + wn*32 + j*8 + 2*c;
                float v0 = acc[i][j][hh*2+0] + bias[n];
                float v1 = acc[i][j][hh*2+1] + bias[n+1];
                if (n < 1024) {
                    float* p = &g_q[((size_t)(bb2*S_+sq))*HID_ + n];
                    p[0] = v0; p[1] = v1;
                } else if (n < 2048) {
                    int nn = n - 1024, hd = nn >> 6, dd = nn & 63;
                    int ir = dd >> 1;
                    float theta = __expf(-(float)ir * (9.210340371976184f / 32.0f));
                    float sn, cs;
                    sincosf((float)sq * theta, &sn, &cs);
                    *(unsigned*)&g_kh[(((size_t)(bb2*NH_+hd))*S_ + sq)*HD_ + dd] =
                        pk(v0*cs - v1*sn, v1*cs + v0*sn);
                } else {
                    int nn = n - 2048, hd = nn >> 6, dd = nn & 63;
                    *(unsigned*)&g_vh[(((size_t)(bb2*NH_+hd))*S_ + sq)*HD_ + dd] = pk(v0, v1);
                }
            }
        }
    }
}

// ---------------- kernel 3: pool+RoPE-Q (->half, pre-scaled) ------------------
__global__ void ropeq_kernel() {
    int idx = blockIdx.x * blockDim.x + threadIdx.x;   // B*NH*SP*32 threads
    int i  = idx & 31;
    int p  = (idx >> 5) & (SP_ - 1);
    int bh = idx >> 15;
    int b = bh >> 4, h = bh & 15;
    int len = g_len[b];
    int s0 = 2 * p;
    int c0 = (s0 < len), c1 = (s0 + 1 < len);
    float norm = (c0 + c1 > 0) ? (float)(c0 + c1) : 1.0f;
    const float2* q0 = (const float2*)(g_q + ((size_t)(b*S_+s0  ))*HID_ + h*HD_) + i;
    const float2* q1 = (const float2*)(g_q + ((size_t)(b*S_+s0+1))*HID_ + h*HD_) + i;
    float2 a = c0 ? *q0 : make_float2(0.f, 0.f);
    float2 c = c1 ? *q1 : make_float2(0.f, 0.f);
    float x0 = (a.x + c.x) / norm;
    float x1 = (a.y + c.y) / norm;
    float theta = __expf(-(float)i * (9.210340371976184f / 32.0f));
    float ang = (float)p * theta;
    float sn, cs;
    sincosf(ang, &sn, &cs);
    *(unsigned*)&g_qh[((size_t)bh*SP_ + p)*HD_ + 2*i] =
        pk((x0*cs - x1*sn)*QSCALE, (x1*cs + x0*sn)*QSCALE);
}

// ---------------- kernel 4: flash attention fp16, ldmatrix + tensor-sum -------
// grid (8, NH, B), 256 thr = 8 warps; warp = 16 q-rows x 128 k-cols.
// smem halfs: Q[128][72] @0; K(buf) @9216+buf*18432; V(buf) @18432+buf*18432.
// V pad cols 64-71 hold 1.0h -> PV n-tile 8 accumulates row sums (= l).
#define ATTN_SMEM (46080*2)   // 92160 B
__global__ __launch_bounds__(256, 2) void attn_h(float* __restrict__ out) {
    extern __shared__ __half hs[];
    const uint32_t sb = smem_u32(hs);
    const int qt = blockIdx.x, h = blockIdx.y, b = blockIdx.z;
    const int len = g_len[b];
    const int tid = threadIdx.x, warp = tid >> 5, lane = tid & 31;
    const int g = lane >> 2, c = lane & 3;
    const int l8  = ((lane >> 3) & 1) * 8;
    const int l16 = ((lane >> 4) & 1) * 8;
    const size_t qhb = (size_t)(b*NH_+h)*SP_*HD_;
    const size_t khb = (size_t)(b*NH_+h)*S_*HD_;

    // Q tile (cp.async) + ones-pads for both V buffers
#pragma unroll
    for (int ii = 0; ii < 4; ii++) {
        int e = tid + ii*256;
        int row = e >> 3, ch = e & 7;
        cp16(sb + (row*72 + ch*8)*2, g_qh + qhb + (size_t)(qt*128+row)*HD_ + ch*8);
    }
#pragma unroll
    for (int ii = 0; ii < 4; ii++) {
        int e = tid + ii*256;                  // 1024 words: 2 bufs x 128 rows x 4
        int bf = e >> 9, row = (e >> 2) & 127, u = e & 3;
        *(unsigned*)&hs[18432 + bf*18432 + row*72 + 64 + u*2] = 0x3C003C00u;
    }
#define KVLOAD(buf, kt) do {                                                       \
        _Pragma("unroll")                                                          \
        for (int ii = 0; ii < 8; ii++) {                                           \
            int e = tid + ii*256;                                                  \
            if (e < 1024) {                                                        \
                int row = e >> 3, ch = e & 7;                                      \
                cp16(sb + (9216 + (buf)*18432 + row*72 + ch*8)*2,                  \
                     g_kh + khb + (size_t)((kt)*128+row)*HD_ + ch*8);              \
            } else {                                                               \
                int e2 = e - 1024;                                                 \
                int row = e2 >> 3, ch = e2 & 7;                                    \
                cp16(sb + (18432 + (buf)*18432 + row*72 + ch*8)*2,                 \
                     g_vh + khb + (size_t)((kt)*128+row)*HD_ + ch*8);              \
            }                                                                      \
        }                                                                          \
    } while (0)
    KVLOAD(0, 0);
    cp_commit();

    float O[9][4];
    float m0 = -1e30f, m1 = -1e30f;
#pragma unroll
    for (int nt = 0; nt < 9; nt++)
#pragma unroll
        for (int r = 0; r < 4; r++) O[nt][r] = 0.0f;

    const int ntiles = (len + 127) >> 7;
    int buf = 0;

    for (int kt = 0; kt < ntiles; kt++) {
        if (kt + 1 < ntiles) { KVLOAD(buf ^ 1, kt + 1); cp_commit(); cp_wait<1>(); }
        else cp_wait<0>();
        __syncthreads();

        // ---- S = Q K^T  (all frags via ldmatrix.x4) ----
        float s[16][4];
#pragma unroll
        for (int nt = 0; nt < 16; nt++)
#pragma unroll
            for (int r = 0; r < 4; r++) s[nt][r] = 0.0f;

        const int kH = 9216 + buf*18432;
#pragma unroll
        for (int ks = 0; ks < 4; ks++) {
            uint32_t ad = sb + ((warp*16 + (lane&7) + l8)*72 + ks*16 + l16)*2;
            unsigned a0, a1, a2, a3;
            ldsm4(a0, a1, a2, a3, ad);
#pragma unroll
            for (int ntp = 0; ntp < 8; ntp++) {
                uint32_t bd = sb + (kH + (ntp*16 + (lane&7) + l16)*72 + ks*16 + l8)*2;
                unsigned b0, b1, b2, b3;
                ldsm4(b0, b1, b2, b3, bd);
                mma_f16(s[2*ntp],   a0, a1, a2, a3, b0, b1);
                mma_f16(s[2*ntp+1], a0, a1, a2, a3, b2, b3);
            }
        }

        // ---- mask partial tile ----
        if (kt == ntiles - 1 && (len & 127)) {
#pragma unroll
            for (int nt = 0; nt < 16; nt++)
#pragma unroll
                for (int cc = 0; cc < 2; cc++) {
                    int kcol = kt*128 + nt*8 + 2*c + cc;
                    if (kcol >= len) { s[nt][cc] = -1e30f; s[nt][2+cc] = -1e30f; }
                }
        }

        // ---- online max + corr ----
        float mx0 = -1e30f, mx1 = -1e30f;
#pragma unroll
        for (int nt = 0; nt < 16; nt++) {
            mx0 = fmaxf(mx0, fmaxf(s[nt][0], s[nt][1]));
            mx1 = fmaxf(mx1, fmaxf(s[nt][2], s[nt][3]));
        }
        mx0 = fmaxf(mx0, __shfl_xor_sync(0xffffffffu, mx0, 1));
        mx0 = fmaxf(mx0, __shfl_xor_sync(0xffffffffu, mx0, 2));
        mx1 = fmaxf(mx1, __shfl_xor_sync(0xffffffffu, mx1, 1));
        mx1 = fmaxf(mx1, __shfl_xor_sync(0xffffffffu, mx1, 2));
        float mn0 = fmaxf(m0, mx0), mn1 = fmaxf(m1, mx1);
        float cr0 = exp2f(m0 - mn0), cr1 = exp2f(m1 - mn1);
        m0 = mn0; m1 = mn1;

        // ---- exp in fp16x2 (packed = PV a-frags) ----
        unsigned ph[16][2];
#pragma unroll
        for (int nt = 0; nt < 16; nt++) {
            ph[nt][0] = ex2h2(pk(s[nt][0] - mn0, s[nt][1] - mn0));
            ph[nt][1] = ex2h2(pk(s[nt][2] - mn1, s[nt][3] - mn1));
        }
#pragma unroll
        for (int nt = 0; nt < 9; nt++) {
            O[nt][0] *= cr0; O[nt][1] *= cr0;
            O[nt][2] *= cr1; O[nt][3] *= cr1;
        }

        // ---- O += P V  (V + ones column via ldmatrix.x4.trans) ----
        const int vH = 18432 + buf*18432;
#pragma unroll
        for (int t = 0; t < 4; t++) {
            unsigned pa0 = ph[4*t][0],   pa1 = ph[4*t][1];
            unsigned pa2 = ph[4*t+1][0], pa3 = ph[4*t+1][1];
            unsigned qa0 = ph[4*t+2][0], qa1 = ph[4*t+2][1];
            unsigned qa2 = ph[4*t+3][0], qa3 = ph[4*t+3][1];
#pragma unroll
            for (int nt = 0; nt < 9; nt++) {
                uint32_t vd = sb + (vH + (t*32 + lane)*72 + nt*8)*2;
                unsigned b0, b1, b2, b3;
                ldsm4t(b0, b1, b2, b3, vd);
                mma_f16(O[nt], pa0, pa1, pa2, pa3, b0, b1);
                mma_f16(O[nt], qa0, qa1, qa2, qa3, b2, b3);
            }
        }
        __syncthreads();
        buf ^= 1;
    }

    // ---- epilogue: l = O[8]; 1/l; q_mask; write ----
    int q0r = qt*128 + warp*16 + g;
    int q1r = q0r + 8;
    float inv0 = (2*q0r < len) ? (1.0f / O[8][0]) : 0.0f;
    float inv1 = (2*q1r < len) ? (1.0f / O[8][2]) : 0.0f;
#pragma unroll
    for (int nt = 0; nt < 8; nt++) {
        int col = h*HD_ + nt*8 + 2*c;
        *(float2*)&out[((size_t)(b*SP_ + q0r))*(NH_*HD_) + col] =
            make_float2(O[nt][0]*inv0, O[nt][1]*inv0);
        *(float2*)&out[((size_t)(b*SP_ + q1r))*(NH_*HD_) + col] =
            make_float2(O[nt][2]*inv1, O[nt][3]*inv1);
    }
}

// ---------------- launcher ----------------------------------------------------
extern "C" void kernel_launch(void* const* d_in, const int* in_sizes, int n_in,
                              void* d_out, int out_size) {
    const float* hidden = (const float*)d_in[0];
    const void*  mask   = d_in[1];
    const float* W      = (const float*)d_in[2];
    const float* bias   = (const float*)d_in[3];
    float* out = (float*)d_out;

    cvtlen_kernel<<<(A4_ + W4_) / 256, 256>>>(hidden, W, mask);

    cudaFuncSetAttribute(qkv_gemm_h, cudaFuncAttributeMaxDynamicSharedMemorySize, GEMM_SMEM);
    dim3 gg(NQKV_/128, (B_*S_)/128);   // (24, 128)
    qkv_gemm_h<<<gg, 256, GEMM_SMEM>>>(bias);

    ropeq_kernel<<<(B_*NH_*SP_*32) / 256, 256>>>();

    cudaFuncSetAttribute(attn_h, cudaFuncAttributeMaxDynamicSharedMemorySize, ATTN_SMEM);
    dim3 ga(SP_/128, NH_, B_);
    attn_h<<<ga, 256, ATTN_SMEM>>>(out);
}

// round 10
// speedup vs baseline: 2.9790x; 1.0442x over previous
#include <cuda_runtime.h>
#include <cuda_fp16.h>
#include <cstdint>
#include <math.h>

#define B_    8
#define S_    2048
#define HID_  1024
#define NH_   16
#define HD_   64
#define SP_   1024
#define NQKV_ 3072
#define QSCALE 0.18033688f   // 0.125 * log2(e)

// ---------------- scratch ----------------------------------------------------
__device__ __half g_ah[B_*S_*HID_];       // half hidden
__device__ __half g_wh[NQKV_*HID_];       // half Wqkv
__device__ float  g_q [B_*S_*HID_];       // q pre-pool f32
__device__ __half g_kh[B_*NH_*S_*HD_];    // roped K half
__device__ __half g_vh[B_*NH_*S_*HD_];    // V half
__device__ float2 g_rope[S_*32];          // (cos, sin) per (pos, freq)
__device__ int    g_len[B_];

// ---------------- helpers -----------------------------------------------------
__device__ __forceinline__ void mma_f16(float* d,
        unsigned a0, unsigned a1, unsigned a2, unsigned a3,
        unsigned b0, unsigned b1) {
    asm volatile("mma.sync.aligned.m16n8k16.row.col.f32.f16.f16.f32 "
        "{%0,%1,%2,%3},{%4,%5,%6,%7},{%8,%9},{%0,%1,%2,%3};\n"
        : "+f"(d[0]), "+f"(d[1]), "+f"(d[2]), "+f"(d[3])
        : "r"(a0), "r"(a1), "r"(a2), "r"(a3), "r"(b0), "r"(b1));
}
__device__ __forceinline__ unsigned pk(float lo, float hi) {
    __half2 h = __floats2half2_rn(lo, hi);
    return *reinterpret_cast<unsigned*>(&h);
}
__device__ __forceinline__ unsigned ex2h2(unsigned x) {
    unsigned r; asm("ex2.approx.f16x2 %0, %1;" : "=r"(r) : "r"(x)); return r;
}
__device__ __forceinline__ uint32_t smem_u32(const void* p) {
    uint32_t a;
    asm("{ .reg .u64 t; cvta.to.shared.u64 t, %1; cvt.u32.u64 %0, t; }"
        : "=r"(a) : "l"(p));
    return a;
}
__device__ __forceinline__ void cp16(uint32_t saddr, const void* gptr) {
    asm volatile("cp.async.cg.shared.global [%0], [%1], 16;"
                 :: "r"(saddr), "l"(gptr));
}
__device__ __forceinline__ void cp_commit() { asm volatile("cp.async.commit_group;"); }
template <int N>
__device__ __forceinline__ void cp_wait() {
    asm volatile("cp.async.wait_group %0;" :: "n"(N));
}
__device__ __forceinline__ void ldsm4(unsigned& r0, unsigned& r1, unsigned& r2,
                                      unsigned& r3, uint32_t addr) {
    asm volatile("ldmatrix.sync.aligned.m8n8.x4.shared.b16 {%0,%1,%2,%3}, [%4];"
        : "=r"(r0), "=r"(r1), "=r"(r2), "=r"(r3) : "r"(addr));
}
__device__ __forceinline__ void ldsm4t(unsigned& r0, unsigned& r1, unsigned& r2,
                                       unsigned& r3, uint32_t addr) {
    asm volatile("ldmatrix.sync.aligned.m8n8.x4.trans.shared.b16 {%0,%1,%2,%3}, [%4];"
        : "=r"(r0), "=r"(r1), "=r"(r2), "=r"(r3) : "r"(addr));
}

// ---------------- kernel 1: half pre-convert + rope table + lengths -----------
#define A4_ (B_*S_*HID_/4)
#define W4_ (NQKV_*HID_/4)
#define RT_ (S_*32)
__global__ void cvtlen_kernel(const float* __restrict__ hidden,
                              const float* __restrict__ W,
                              const void*  __restrict__ mask) {
    int i = blockIdx.x * 256 + threadIdx.x;
    if (i < A4_) {
        float4 v = ((const float4*)hidden)[i];
        ((uint2*)g_ah)[i] = make_uint2(pk(v.x, v.y), pk(v.z, v.w));
    } else if (i < A4_ + W4_) {
        int j = i - A4_;
        float4 v = ((const float4*)W)[j];
        ((uint2*)g_wh)[j] = make_uint2(pk(v.x, v.y), pk(v.z, v.w));
    } else {
        int e = i - A4_ - W4_;
        if (e < RT_) {
            int s = e >> 5, ir = e & 31;
            float theta = __expf(-(float)ir * (9.210340371976184f / 32.0f));
            float sn, cs;
            sincosf((float)s * theta, &sn, &cs);
            g_rope[e] = make_float2(cs, sn);
        }
    }
    if (blockIdx.x == 0) {
        __shared__ int sred[256];
        const int* mi = (const int*)mask;
        int w = mi[16];
        int mode = (w == 1) ? 0 : ((w == 0x3F800000) ? 1 : 2);
        for (int b = 0; b < B_; b++) {
            int cnt = 0;
            for (int s = threadIdx.x; s < S_; s += 256) {
                int v;
                if (mode == 0)      v = (mi[b*S_+s] != 0);
                else if (mode == 1) v = (((const float*)mask)[b*S_+s] != 0.0f);
                else                v = (((const unsigned char*)mask)[b*S_+s] != 0);
                cnt += v;
            }
            sred[threadIdx.x] = cnt;
            __syncthreads();
            for (int st = 128; st > 0; st >>= 1) {
                if (threadIdx.x < st) sred[threadIdx.x] += sred[threadIdx.x + st];
                __syncthreads();
            }
            if (threadIdx.x == 0) g_len[b] = sred[0];
            __syncthreads();
        }
    }
}

// ---------------- kernel 2: QKV GEMM fp16, 128x128 tile, BK=64, 3-stage -------
// 256 threads = 8 warps (2x4), warp 64x32, 2 CTAs/SM.
#define AST_H (128*72)              // halfs per stage (pitch 72)
#define BSTART (3*AST_H)
#define GEMM_SMEM (6*AST_H*2)       // 110592 B
__global__ __launch_bounds__(256, 2) void qkv_gemm_h(const float* __restrict__ bias) {
    extern __shared__ __half hs[];
    const uint32_t sb = smem_u32(hs);
    const int tid = threadIdx.x, warp = tid >> 5, lane = tid & 31;
    const int wm = warp >> 2, wn = warp & 3;
    const int g = lane >> 2, c = lane & 3;
    const int bm = blockIdx.y, bn = blockIdx.x;
    const __half* Ab = g_ah + (size_t)bm * 128 * HID_;
    const __half* Wb = g_wh + (size_t)bn * 128 * HID_;

#define GISSUE(st, kt) do {                                                        \
        _Pragma("unroll")                                                          \
        for (int ii = 0; ii < 8; ii++) {                                           \
            int e = tid + ii*256;                                                  \
            if (e < 1024) {                                                        \
                int row = e >> 3, ch = e & 7;                                      \
                cp16(sb + ((st)*AST_H + row*72 + ch*8)*2,                          \
                     Ab + (size_t)row*HID_ + (kt)*64 + ch*8);                      \
            } else {                                                               \
                int e2 = e - 1024;                                                 \
                int row = e2 >> 3, ch = e2 & 7;                                    \
                cp16(sb + (BSTART + (st)*AST_H + row*72 + ch*8)*2,                 \
                     Wb + (size_t)row*HID_ + (kt)*64 + ch*8);                      \
            }                                                                      \
        }                                                                          \
    } while (0)

    float acc[4][4][4];
#pragma unroll
    for (int i = 0; i < 4; i++)
#pragma unroll
        for (int j = 0; j < 4; j++)
#pragma unroll
            for (int r = 0; r < 4; r++) acc[i][j][r] = 0.0f;

    GISSUE(0, 0); cp_commit();
    GISSUE(1, 1); cp_commit();

    const int l8  = ((lane >> 3) & 1) * 8;
    const int l16 = ((lane >> 4) & 1) * 8;
    for (int kt = 0; kt < 16; kt++) {
        if (kt + 1 < 16) cp_wait<1>(); else cp_wait<0>();
        __syncthreads();
        if (kt + 2 < 16) { GISSUE((kt + 2) % 3, kt + 2); cp_commit(); }

        const uint32_t abase = sb + ((kt % 3) * AST_H) * 2;
        const uint32_t bbase = sb + (BSTART + (kt % 3) * AST_H) * 2;
#pragma unroll
        for (int ks = 0; ks < 4; ks++) {
            unsigned a[4][4], bf[4][2];
#pragma unroll
            for (int i = 0; i < 4; i++) {
                uint32_t ad = abase +
                    ((wm*64 + i*16 + (lane&7) + l8)*72 + ks*16 + l16)*2;
                ldsm4(a[i][0], a[i][1], a[i][2], a[i][3], ad);
            }
#pragma unroll
            for (int jp = 0; jp < 2; jp++) {
                uint32_t bd = bbase +
                    ((wn*32 + jp*16 + (lane&7) + l16)*72 + ks*16 + l8)*2;
                ldsm4(bf[2*jp][0], bf[2*jp][1], bf[2*jp+1][0], bf[2*jp+1][1], bd);
            }
#pragma unroll
            for (int i = 0; i < 4; i++)
#pragma unroll
                for (int j = 0; j < 4; j++)
                    mma_f16(acc[i][j], a[i][0], a[i][1], a[i][2], a[i][3],
                            bf[j][0], bf[j][1]);
        }
    }

    // epilogue: bias; q -> f32 staging; K -> RoPE (table) -> half; V -> half
#pragma unroll
    for (int i = 0; i < 4; i++) {
#pragma unroll
        for (int hh = 0; hh < 2; hh++) {
            int m = bm*128 + wm*64 + i*16 + hh*8 + g;
            int bb2 = m >> 11;
            int sq = m & 2047;
#pragma unroll
            for (int j = 0; j < 4; j++) {
                int n = bn*128 + wn*32 + j*8 + 2*c;
                float v0 = acc[i][j][hh*2+0] + bias[n];
                float v1 = acc[i][j][hh*2+1] + bias[n+1];
                if (n < 1024) {
                    float* p = &g_q[((size_t)(bb2*S_+sq))*HID_ + n];
                    p[0] = v0; p[1] = v1;
                } else if (n < 2048) {
                    int nn = n - 1024, hd = nn >> 6, dd = nn & 63;
                    float2 cs = g_rope[sq*32 + (dd >> 1)];
                    *(unsigned*)&g_kh[(((size_t)(bb2*NH_+hd))*S_ + sq)*HD_ + dd] =
                        pk(v0*cs.x - v1*cs.y, v1*cs.x + v0*cs.y);
                } else {
                    int nn = n - 2048, hd = nn >> 6, dd = nn & 63;
                    *(unsigned*)&g_vh[(((size_t)(bb2*NH_+hd))*S_ + sq)*HD_ + dd] = pk(v0, v1);
                }
            }
        }
    }
}

// ---------------- kernel 3: flash attention fp16, fused pool+RoPE-Q -----------
// grid (8, NH, B), 256 thr = 8 warps; warp = 16 q-rows x 128 k-cols.
// smem halfs: Q[128][72] @0; K(buf) @9216+buf*18432; V(buf) @18432+buf*18432.
// V pad cols 64-71 hold 1.0h -> PV n-tile 8 accumulates row sums (= l).
#define ATTN_SMEM (46080*2)   // 92160 B
__global__ __launch_bounds__(256, 2) void attn_h(float* __restrict__ out) {
    extern __shared__ __half hs[];
    const uint32_t sb = smem_u32(hs);
    const int qt = blockIdx.x, h = blockIdx.y, b = blockIdx.z;
    const int len = g_len[b];
    const int tid = threadIdx.x, warp = tid >> 5, lane = tid & 31;
    const int g = lane >> 2, c = lane & 3;
    const int l8  = ((lane >> 3) & 1) * 8;
    const int l16 = ((lane >> 4) & 1) * 8;
    const size_t khb = (size_t)(b*NH_+h)*S_*HD_;

#define KVLOAD(buf, kt) do {                                                       \
        _Pragma("unroll")                                                          \
        for (int ii = 0; ii < 8; ii++) {                                           \
            int e = tid + ii*256;                                                  \
            if (e < 1024) {                                                        \
                int row = e >> 3, ch = e & 7;                                      \
                cp16(sb + (9216 + (buf)*18432 + row*72 + ch*8)*2,                  \
                     g_kh + khb + (size_t)((kt)*128+row)*HD_ + ch*8);              \
            } else {                                                               \
                int e2 = e - 1024;                                                 \
                int row = e2 >> 3, ch = e2 & 7;                                    \
                cp16(sb + (18432 + (buf)*18432 + row*72 + ch*8)*2,                 \
                     g_vh + khb + (size_t)((kt)*128+row)*HD_ + ch*8);              \
            }                                                                      \
        }                                                                          \
    } while (0)
    KVLOAD(0, 0);
    cp_commit();

    // fused pool + RoPE + scale for Q tile (overlaps the KV loads above)
#pragma unroll
    for (int ii = 0; ii < 16; ii++) {
        int e = tid + ii*256;                  // 4096 = 128 rows x 32 pairs
        int r = e >> 5, i = e & 31;
        int p = qt*128 + r;
        int s0 = 2 * p;
        int c0 = (s0 < len), c1 = (s0 + 1 < len);
        float norm = (c0 + c1 > 0) ? (float)(c0 + c1) : 1.0f;
        const float* row0 = g_q + ((size_t)(b*S_+s0))*HID_ + h*HD_ + 2*i;
        float2 a = c0 ? *(const float2*)row0 : make_float2(0.f, 0.f);
        float2 d = c1 ? *(const float2*)(row0 + HID_) : make_float2(0.f, 0.f);
        float x0 = (a.x + d.x) / norm;
        float x1 = (a.y + d.y) / norm;
        float2 cs = g_rope[p*32 + i];
        *(unsigned*)&hs[r*72 + 2*i] =
            pk((x0*cs.x - x1*cs.y)*QSCALE, (x1*cs.x + x0*cs.y)*QSCALE);
    }
    // ones-pads for both V buffers
#pragma unroll
    for (int ii = 0; ii < 4; ii++) {
        int e = tid + ii*256;                  // 1024 words: 2 bufs x 128 rows x 4
        int bf = e >> 9, row = (e >> 2) & 127, u = e & 3;
        *(unsigned*)&hs[18432 + bf*18432 + row*72 + 64 + u*2] = 0x3C003C00u;
    }

    float O[9][4];
    float m0 = -1e30f, m1 = -1e30f;
#pragma unroll
    for (int nt = 0; nt < 9; nt++)
#pragma unroll
        for (int r = 0; r < 4; r++) O[nt][r] = 0.0f;

    const int ntiles = (len + 127) >> 7;
    int buf = 0;

    for (int kt = 0; kt < ntiles; kt++) {
        if (kt + 1 < ntiles) { KVLOAD(buf ^ 1, kt + 1); cp_commit(); cp_wait<1>(); }
        else cp_wait<0>();
        __syncthreads();

        // ---- S = Q K^T  (all frags via ldmatrix.x4) ----
        float s[16][4];
#pragma unroll
        for (int nt = 0; nt < 16; nt++)
#pragma unroll
            for (int r = 0; r < 4; r++) s[nt][r] = 0.0f;

        const int kH = 9216 + buf*18432;
#pragma unroll
        for (int ks = 0; ks < 4; ks++) {
            uint32_t ad = sb + ((warp*16 + (lane&7) + l8)*72 + ks*16 + l16)*2;
            unsigned a0, a1, a2, a3;
            ldsm4(a0, a1, a2, a3, ad);
#pragma unroll
            for (int ntp = 0; ntp < 8; ntp++) {
                uint32_t bd = sb + (kH + (ntp*16 + (lane&7) + l16)*72 + ks*16 + l8)*2;
                unsigned b0, b1, b2, b3;
                ldsm4(b0, b1, b2, b3, bd);
                mma_f16(s[2*ntp],   a0, a1, a2, a3, b0, b1);
                mma_f16(s[2*ntp+1], a0, a1, a2, a3, b2, b3);
            }
        }

        // ---- mask partial tile ----
        if (kt == ntiles - 1 && (len & 127)) {
#pragma unroll
            for (int nt = 0; nt < 16; nt++)
#pragma unroll
                for (int cc = 0; cc < 2; cc++) {
                    int kcol = kt*128 + nt*8 + 2*c + cc;
                    if (kcol >= len) { s[nt][cc] = -1e30f; s[nt][2+cc] = -1e30f; }
                }
        }

        // ---- online max + corr ----
        float mx0 = -1e30f, mx1 = -1e30f;
#pragma unroll
        for (int nt = 0; nt < 16; nt++) {
            mx0 = fmaxf(mx0, fmaxf(s[nt][0], s[nt][1]));
            mx1 = fmaxf(mx1, fmaxf(s[nt][2], s[nt][3]));
        }
        mx0 = fmaxf(mx0, __shfl_xor_sync(0xffffffffu, mx0, 1));
        mx0 = fmaxf(mx0, __shfl_xor_sync(0xffffffffu, mx0, 2));
        mx1 = fmaxf(mx1, __shfl_xor_sync(0xffffffffu, mx1, 1));
        mx1 = fmaxf(mx1, __shfl_xor_sync(0xffffffffu, mx1, 2));
        float mn0 = fmaxf(m0, mx0), mn1 = fmaxf(m1, mx1);
        float cr0 = exp2f(m0 - mn0), cr1 = exp2f(m1 - mn1);
        m0 = mn0; m1 = mn1;

        // ---- exp in fp16x2 (packed = PV a-frags) ----
        unsigned ph[16][2];
#pragma unroll
        for (int nt = 0; nt < 16; nt++) {
            ph[nt][0] = ex2h2(pk(s[nt][0] - mn0, s[nt][1] - mn0));
            ph[nt][1] = ex2h2(pk(s[nt][2] - mn1, s[nt][3] - mn1));
        }
#pragma unroll
        for (int nt = 0; nt < 9; nt++) {
            O[nt][0] *= cr0; O[nt][1] *= cr0;
            O[nt][2] *= cr1; O[nt][3] *= cr1;
        }

        // ---- O += P V  (V + ones column via ldmatrix.x4.trans) ----
        const int vH = 18432 + buf*18432;
#pragma unroll
        for (int t = 0; t < 4; t++) {
            unsigned pa0 = ph[4*t][0],   pa1 = ph[4*t][1];
            unsigned pa2 = ph[4*t+1][0], pa3 = ph[4*t+1][1];
            unsigned qa0 = ph[4*t+2][0], qa1 = ph[4*t+2][1];
            unsigned qa2 = ph[4*t+3][0], qa3 = ph[4*t+3][1];
#pragma unroll
            for (int nt = 0; nt < 9; nt++) {
                uint32_t vd = sb + (vH + (t*32 + lane)*72 + nt*8)*2;
                unsigned b0, b1, b2, b3;
                ldsm4t(b0, b1, b2, b3, vd);
                mma_f16(O[nt], pa0, pa1, pa2, pa3, b0, b1);
                mma_f16(O[nt], qa0, qa1, qa2, qa3, b2, b3);
            }
        }
        __syncthreads();
        buf ^= 1;
    }

    // ---- epilogue: l = O[8]; 1/l; q_mask; write ----
    int q0r = qt*128 + warp*16 + g;
    int q1r = q0r + 8;
    float inv0 = (2*q0r < len) ? (1.0f / O[8][0]) : 0.0f;
    float inv1 = (2*q1r < len) ? (1.0f / O[8][2]) : 0.0f;
#pragma unroll
    for (int nt = 0; nt < 8; nt++) {
        int col = h*HD_ + nt*8 + 2*c;
        *(float2*)&out[((size_t)(b*SP_ + q0r))*(NH_*HD_) + col] =
            make_float2(O[nt][0]*inv0, O[nt][1]*inv0);
        *(float2*)&out[((size_t)(b*SP_ + q1r))*(NH_*HD_) + col] =
            make_float2(O[nt][2]*inv1, O[nt][3]*inv1);
    }
}

// ---------------- launcher ----------------------------------------------------
extern "C" void kernel_launch(void* const* d_in, const int* in_sizes, int n_in,
                              void* d_out, int out_size) {
    const float* hidden = (const float*)d_in[0];
    const void*  mask   = d_in[1];
    const float* W      = (const float*)d_in[2];
    const float* bias   = (const float*)d_in[3];
    float* out = (float*)d_out;

    cvtlen_kernel<<<(A4_ + W4_ + RT_) / 256, 256>>>(hidden, W, mask);

    cudaFuncSetAttribute(qkv_gemm_h, cudaFuncAttributeMaxDynamicSharedMemorySize, GEMM_SMEM);
    dim3 gg(NQKV_/128, (B_*S_)/128);   // (24, 128)
    qkv_gemm_h<<<gg, 256, GEMM_SMEM>>>(bias);

    cudaFuncSetAttribute(attn_h, cudaFuncAttributeMaxDynamicSharedMemorySize, ATTN_SMEM);
    dim3 ga(SP_/128, NH_, B_);
    attn_h<<<ga, 256, ATTN_SMEM>>>(out);
}

// round 11
// speedup vs baseline: 3.3034x; 1.1089x over previous
#include <cuda_runtime.h>
#include <cuda_fp16.h>
#include <cstdint>
#include <math.h>

#define B_    8
#define S_    2048
#define HID_  1024
#define NH_   16
#define HD_   64
#define SP_   1024
#define NQKV_ 3072
#define QSCALE 0.18033688f   // 0.125 * log2(e)

// ---------------- scratch ----------------------------------------------------
__device__ __half g_ah[B_*S_*HID_];       // half hidden
__device__ __half g_wh[NQKV_*HID_];       // half Wqkv
__device__ float  g_q [B_*S_*HID_];       // q pre-pool f32
__device__ __half g_kh[B_*NH_*S_*HD_];    // roped K half
__device__ __half g_vh[B_*NH_*S_*HD_];    // V half
__device__ float2 g_rope[S_*32];          // (cos, sin) per (pos, freq)
__device__ int    g_len[B_];

// ---------------- helpers -----------------------------------------------------
__device__ __forceinline__ void mma_f16(float* d,
        unsigned a0, unsigned a1, unsigned a2, unsigned a3,
        unsigned b0, unsigned b1) {
    asm volatile("mma.sync.aligned.m16n8k16.row.col.f32.f16.f16.f32 "
        "{%0,%1,%2,%3},{%4,%5,%6,%7},{%8,%9},{%0,%1,%2,%3};\n"
        : "+f"(d[0]), "+f"(d[1]), "+f"(d[2]), "+f"(d[3])
        : "r"(a0), "r"(a1), "r"(a2), "r"(a3), "r"(b0), "r"(b1));
}
__device__ __forceinline__ unsigned pk(float lo, float hi) {
    __half2 h = __floats2half2_rn(lo, hi);
    return *reinterpret_cast<unsigned*>(&h);
}
__device__ __forceinline__ unsigned ex2h2(unsigned x) {
    unsigned r; asm("ex2.approx.f16x2 %0, %1;" : "=r"(r) : "r"(x)); return r;
}
__device__ __forceinline__ uint32_t smem_u32(const void* p) {
    uint32_t a;
    asm("{ .reg .u64 t; cvta.to.shared.u64 t, %1; cvt.u32.u64 %0, t; }"
        : "=r"(a) : "l"(p));
    return a;
}
__device__ __forceinline__ void cp16(uint32_t saddr, const void* gptr) {
    asm volatile("cp.async.cg.shared.global [%0], [%1], 16;"
                 :: "r"(saddr), "l"(gptr));
}
__device__ __forceinline__ void cp_commit() { asm volatile("cp.async.commit_group;"); }
template <int N>
__device__ __forceinline__ void cp_wait() {
    asm volatile("cp.async.wait_group %0;" :: "n"(N));
}
__device__ __forceinline__ void ldsm4(unsigned& r0, unsigned& r1, unsigned& r2,
                                      unsigned& r3, uint32_t addr) {
    asm volatile("ldmatrix.sync.aligned.m8n8.x4.shared.b16 {%0,%1,%2,%3}, [%4];"
        : "=r"(r0), "=r"(r1), "=r"(r2), "=r"(r3) : "r"(addr));
}
__device__ __forceinline__ void ldsm4t(unsigned& r0, unsigned& r1, unsigned& r2,
                                       unsigned& r3, uint32_t addr) {
    asm volatile("ldmatrix.sync.aligned.m8n8.x4.trans.shared.b16 {%0,%1,%2,%3}, [%4];"
        : "=r"(r0), "=r"(r1), "=r"(r2), "=r"(r3) : "r"(addr));
}

// ---------------- kernel 1: half pre-convert + rope table + lengths -----------
#define A4_ (B_*S_*HID_/4)
#define W4_ (NQKV_*HID_/4)
#define RT_ (S_*32)
__global__ void cvtlen_kernel(const float* __restrict__ hidden,
                              const float* __restrict__ W,
                              const void*  __restrict__ mask) {
    int i = blockIdx.x * 256 + threadIdx.x;
    if (i < A4_) {
        float4 v = ((const float4*)hidden)[i];
        ((uint2*)g_ah)[i] = make_uint2(pk(v.x, v.y), pk(v.z, v.w));
    } else if (i < A4_ + W4_) {
        int j = i - A4_;
        float4 v = ((const float4*)W)[j];
        ((uint2*)g_wh)[j] = make_uint2(pk(v.x, v.y), pk(v.z, v.w));
    } else {
        int e = i - A4_ - W4_;
        if (e < RT_) {
            int s = e >> 5, ir = e & 31;
            float theta = __expf(-(float)ir * (9.210340371976184f / 32.0f));
            float sn, cs;
            sincosf((float)s * theta, &sn, &cs);
            g_rope[e] = make_float2(cs, sn);
        }
    }
    if (blockIdx.x == 0) {
        __shared__ int sred[256];
        const int* mi = (const int*)mask;
        int w = mi[16];
        int mode = (w == 1) ? 0 : ((w == 0x3F800000) ? 1 : 2);
        for (int b = 0; b < B_; b++) {
            int cnt = 0;
            for (int s = threadIdx.x; s < S_; s += 256) {
                int v;
                if (mode == 0)      v = (mi[b*S_+s] != 0);
                else if (mode == 1) v = (((const float*)mask)[b*S_+s] != 0.0f);
                else                v = (((const unsigned char*)mask)[b*S_+s] != 0);
                cnt += v;
            }
            sred[threadIdx.x] = cnt;
            __syncthreads();
            for (int st = 128; st > 0; st >>= 1) {
                if (threadIdx.x < st) sred[threadIdx.x] += sred[threadIdx.x + st];
                __syncthreads();
            }
            if (threadIdx.x == 0) g_len[b] = sred[0];
            __syncthreads();
        }
    }
}

// ---------------- kernel 2: QKV GEMM fp16, 128x128 tile, BK=64, 3-stage -------
// 256 threads = 8 warps (2x4), warp 64x32, 2 CTAs/SM.
// Early-exit: M-block rows are 128 contiguous s of one batch; if s0 >= len[b],
// nothing downstream ever reads these outputs (attn ntiles/mask + q_mask).
#define AST_H (128*72)              // halfs per stage (pitch 72)
#define BSTART (3*AST_H)
#define GEMM_SMEM (6*AST_H*2)       // 110592 B
__global__ __launch_bounds__(256, 2) void qkv_gemm_h(const float* __restrict__ bias) {
    const int bm = blockIdx.y, bn = blockIdx.x;
    {
        int bb0 = (bm*128) >> 11;
        int s00 = (bm*128) & 2047;
        if (s00 >= g_len[bb0]) return;     // dead rows: outputs never read
    }
    extern __shared__ __half hs[];
    const uint32_t sb = smem_u32(hs);
    const int tid = threadIdx.x, warp = tid >> 5, lane = tid & 31;
    const int wm = warp >> 2, wn = warp & 3;
    const int g = lane >> 2, c = lane & 3;
    const __half* Ab = g_ah + (size_t)bm * 128 * HID_;
    const __half* Wb = g_wh + (size_t)bn * 128 * HID_;

#define GISSUE(st, kt) do {                                                        \
        _Pragma("unroll")                                                          \
        for (int ii = 0; ii < 8; ii++) {                                           \
            int e = tid + ii*256;                                                  \
            if (e < 1024) {                                                        \
                int row = e >> 3, ch = e & 7;                                      \
                cp16(sb + ((st)*AST_H + row*72 + ch*8)*2,                          \
                     Ab + (size_t)row*HID_ + (kt)*64 + ch*8);                      \
            } else {                                                               \
                int e2 = e - 1024;                                                 \
                int row = e2 >> 3, ch = e2 & 7;                                    \
                cp16(sb + (BSTART + (st)*AST_H + row*72 + ch*8)*2,                 \
                     Wb + (size_t)row*HID_ + (kt)*64 + ch*8);                      \
            }                                                                      \
        }                                                                          \
    } while (0)

    float acc[4][4][4];
#pragma unroll
    for (int i = 0; i < 4; i++)
#pragma unroll
        for (int j = 0; j < 4; j++)
#pragma unroll
            for (int r = 0; r < 4; r++) acc[i][j][r] = 0.0f;

    GISSUE(0, 0); cp_commit();
    GISSUE(1, 1); cp_commit();

    const int l8  = ((lane >> 3) & 1) * 8;
    const int l16 = ((lane >> 4) & 1) * 8;
    for (int kt = 0; kt < 16; kt++) {
        if (kt + 1 < 16) cp_wait<1>(); else cp_wait<0>();
        __syncthreads();
        if (kt + 2 < 16) { GISSUE((kt + 2) % 3, kt + 2); cp_commit(); }

        const uint32_t abase = sb + ((kt % 3) * AST_H) * 2;
        const uint32_t bbase = sb + (BSTART + (kt % 3) * AST_H) * 2;
#pragma unroll
        for (int ks = 0; ks < 4; ks++) {
            unsigned a[4][4], bf[4][2];
#pragma unroll
            for (int i = 0; i < 4; i++) {
                uint32_t ad = abase +
                    ((wm*64 + i*16 + (lane&7) + l8)*72 + ks*16 + l16)*2;
                ldsm4(a[i][0], a[i][1], a[i][2], a[i][3], ad);
            }
#pragma unroll
            for (int jp = 0; jp < 2; jp++) {
                uint32_t bd = bbase +
                    ((wn*32 + jp*16 + (lane&7) + l16)*72 + ks*16 + l8)*2;
                ldsm4(bf[2*jp][0], bf[2*jp][1], bf[2*jp+1][0], bf[2*jp+1][1], bd);
            }
#pragma unroll
            for (int i = 0; i < 4; i++)
#pragma unroll
                for (int j = 0; j < 4; j++)
                    mma_f16(acc[i][j], a[i][0], a[i][1], a[i][2], a[i][3],
                            bf[j][0], bf[j][1]);
        }
    }

    // epilogue: bias; q -> f32 staging; K -> RoPE (table) -> half; V -> half
#pragma unroll
    for (int i = 0; i < 4; i++) {
#pragma unroll
        for (int hh = 0; hh < 2; hh++) {
            int m = bm*128 + wm*64 + i*16 + hh*8 + g;
            int bb2 = m >> 11;
            int sq = m & 2047;
#pragma unroll
            for (int j = 0; j < 4; j++) {
                int n = bn*128 + wn*32 + j*8 + 2*c;
                float v0 = acc[i][j][hh*2+0] + bias[n];
                float v1 = acc[i][j][hh*2+1] + bias[n+1];
                if (n < 1024) {
                    float* p = &g_q[((size_t)(bb2*S_+sq))*HID_ + n];
                    p[0] = v0; p[1] = v1;
                } else if (n < 2048) {
                    int nn = n - 1024, hd = nn >> 6, dd = nn & 63;
                    float2 cs = g_rope[sq*32 + (dd >> 1)];
                    *(unsigned*)&g_kh[(((size_t)(bb2*NH_+hd))*S_ + sq)*HD_ + dd] =
                        pk(v0*cs.x - v1*cs.y, v1*cs.x + v0*cs.y);
                } else {
                    int nn = n - 2048, hd = nn >> 6, dd = nn & 63;
                    *(unsigned*)&g_vh[(((size_t)(bb2*NH_+hd))*S_ + sq)*HD_ + dd] = pk(v0, v1);
                }
            }
        }
    }
}

// ---------------- kernel 3: flash attention fp16, fused pool+RoPE-Q -----------
// grid (8, NH, B), 256 thr = 8 warps; warp = 16 q-rows x 128 k-cols.
// smem halfs: Q[128][72] @0; K(buf) @9216+buf*18432; V(buf) @18432+buf*18432.
// V pad cols 64-71 hold 1.0h -> PV n-tile 8 accumulates row sums (= l).
#define ATTN_SMEM (46080*2)   // 92160 B
__global__ __launch_bounds__(256, 2) void attn_h(float* __restrict__ out) {
    extern __shared__ __half hs[];
    const uint32_t sb = smem_u32(hs);
    const int qt = blockIdx.x, h = blockIdx.y, b = blockIdx.z;
    const int len = g_len[b];
    const int tid = threadIdx.x, warp = tid >> 5, lane = tid & 31;
    const int g = lane >> 2, c = lane & 3;
    const int l8  = ((lane >> 3) & 1) * 8;
    const int l16 = ((lane >> 4) & 1) * 8;
    const size_t khb = (size_t)(b*NH_+h)*S_*HD_;

#define KVLOAD(buf, kt) do {                                                       \
        _Pragma("unroll")                                                          \
        for (int ii = 0; ii < 8; ii++) {                                           \
            int e = tid + ii*256;                                                  \
            if (e < 1024) {                                                        \
                int row = e >> 3, ch = e & 7;                                      \
                cp16(sb + (9216 + (buf)*18432 + row*72 + ch*8)*2,                  \
                     g_kh + khb + (size_t)((kt)*128+row)*HD_ + ch*8);              \
            } else {                                                               \
                int e2 = e - 1024;                                                 \
                int row = e2 >> 3, ch = e2 & 7;                                    \
                cp16(sb + (18432 + (buf)*18432 + row*72 + ch*8)*2,                 \
                     g_vh + khb + (size_t)((kt)*128+row)*HD_ + ch*8);              \
            }                                                                      \
        }                                                                          \
    } while (0)
    KVLOAD(0, 0);
    cp_commit();

    // fused pool + RoPE + scale for Q tile (overlaps the KV loads above)
#pragma unroll
    for (int ii = 0; ii < 16; ii++) {
        int e = tid + ii*256;                  // 4096 = 128 rows x 32 pairs
        int r = e >> 5, i = e & 31;
        int p = qt*128 + r;
        int s0 = 2 * p;
        int c0 = (s0 < len), c1 = (s0 + 1 < len);
        float norm = (c0 + c1 > 0) ? (float)(c0 + c1) : 1.0f;
        const float* row0 = g_q + ((size_t)(b*S_+s0))*HID_ + h*HD_ + 2*i;
        float2 a = c0 ? *(const float2*)row0 : make_float2(0.f, 0.f);
        float2 d = c1 ? *(const float2*)(row0 + HID_) : make_float2(0.f, 0.f);
        float x0 = (a.x + d.x) / norm;
        float x1 = (a.y + d.y) / norm;
        float2 cs = g_rope[p*32 + i];
        *(unsigned*)&hs[r*72 + 2*i] =
            pk((x0*cs.x - x1*cs.y)*QSCALE, (x1*cs.x + x0*cs.y)*QSCALE);
    }
    // ones-pads for both V buffers
#pragma unroll
    for (int ii = 0; ii < 4; ii++) {
        int e = tid + ii*256;                  // 1024 words: 2 bufs x 128 rows x 4
        int bf = e >> 9, row = (e >> 2) & 127, u = e & 3;
        *(unsigned*)&hs[18432 + bf*18432 + row*72 + 64 + u*2] = 0x3C003C00u;
    }

    float O[9][4];
    float m0 = -1e30f, m1 = -1e30f;
#pragma unroll
    for (int nt = 0; nt < 9; nt++)
#pragma unroll
        for (int r = 0; r < 4; r++) O[nt][r] = 0.0f;

    const int ntiles = (len + 127) >> 7;
    int buf = 0;

    for (int kt = 0; kt < ntiles; kt++) {
        if (kt + 1 < ntiles) { KVLOAD(buf ^ 1, kt + 1); cp_commit(); cp_wait<1>(); }
        else cp_wait<0>();
        __syncthreads();

        // ---- S = Q K^T  (all frags via ldmatrix.x4) ----
        float s[16][4];
#pragma unroll
        for (int nt = 0; nt < 16; nt++)
#pragma unroll
            for (int r = 0; r < 4; r++) s[nt][r] = 0.0f;

        const int kH = 9216 + buf*18432;
#pragma unroll
        for (int ks = 0; ks < 4; ks++) {
            uint32_t ad = sb + ((warp*16 + (lane&7) + l8)*72 + ks*16 + l16)*2;
            unsigned a0, a1, a2, a3;
            ldsm4(a0, a1, a2, a3, ad);
#pragma unroll
            for (int ntp = 0; ntp < 8; ntp++) {
                uint32_t bd = sb + (kH + (ntp*16 + (lane&7) + l16)*72 + ks*16 + l8)*2;
                unsigned b0, b1, b2, b3;
                ldsm4(b0, b1, b2, b3, bd);
                mma_f16(s[2*ntp],   a0, a1, a2, a3, b0, b1);
                mma_f16(s[2*ntp+1], a0, a1, a2, a3, b2, b3);
            }
        }

        // ---- mask partial tile ----
        if (kt == ntiles - 1 && (len & 127)) {
#pragma unroll
            for (int nt = 0; nt < 16; nt++)
#pragma unroll
                for (int cc = 0; cc < 2; cc++) {
                    int kcol = kt*128 + nt*8 + 2*c + cc;
                    if (kcol >= len) { s[nt][cc] = -1e30f; s[nt][2+cc] = -1e30f; }
                }
        }

        // ---- online max + corr ----
        float mx0 = -1e30f, mx1 = -1e30f;
#pragma unroll
        for (int nt = 0; nt < 16; nt++) {
            mx0 = fmaxf(mx0, fmaxf(s[nt][0], s[nt][1]));
            mx1 = fmaxf(mx1, fmaxf(s[nt][2], s[nt][3]));
        }
        mx0 = fmaxf(mx0, __shfl_xor_sync(0xffffffffu, mx0, 1));
        mx0 = fmaxf(mx0, __shfl_xor_sync(0xffffffffu, mx0, 2));
        mx1 = fmaxf(mx1, __shfl_xor_sync(0xffffffffu, mx1, 1));
        mx1 = fmaxf(mx1, __shfl_xor_sync(0xffffffffu, mx1, 2));
        float mn0 = fmaxf(m0, mx0), mn1 = fmaxf(m1, mx1);
        float cr0 = exp2f(m0 - mn0), cr1 = exp2f(m1 - mn1);
        m0 = mn0; m1 = mn1;

        // ---- exp in fp16x2 (packed = PV a-frags) ----
        unsigned ph[16][2];
#pragma unroll
        for (int nt = 0; nt < 16; nt++) {
            ph[nt][0] = ex2h2(pk(s[nt][0] - mn0, s[nt][1] - mn0));
            ph[nt][1] = ex2h2(pk(s[nt][2] - mn1, s[nt][3] - mn1));
        }
#pragma unroll
        for (int nt = 0; nt < 9; nt++) {
            O[nt][0] *= cr0; O[nt][1] *= cr0;
            O[nt][2] *= cr1; O[nt][3] *= cr1;
        }

        // ---- O += P V  (V + ones column via ldmatrix.x4.trans) ----
        const int vH = 18432 + buf*18432;
#pragma unroll
        for (int t = 0; t < 4; t++) {
            unsigned pa0 = ph[4*t][0],   pa1 = ph[4*t][1];
            unsigned pa2 = ph[4*t+1][0], pa3 = ph[4*t+1][1];
            unsigned qa0 = ph[4*t+2][0], qa1 = ph[4*t+2][1];
            unsigned qa2 = ph[4*t+3][0], qa3 = ph[4*t+3][1];
#pragma unroll
            for (int nt = 0; nt < 9; nt++) {
                uint32_t vd = sb + (vH + (t*32 + lane)*72 + nt*8)*2;
                unsigned b0, b1, b2, b3;
                ldsm4t(b0, b1, b2, b3, vd);
                mma_f16(O[nt], pa0, pa1, pa2, pa3, b0, b1);
                mma_f16(O[nt], qa0, qa1, qa2, qa3, b2, b3);
            }
        }
        __syncthreads();
        buf ^= 1;
    }

    // ---- epilogue: l = O[8]; 1/l; q_mask; write ----
    int q0r = qt*128 + warp*16 + g;
    int q1r = q0r + 8;
    float inv0 = (2*q0r < len) ? (1.0f / O[8][0]) : 0.0f;
    float inv1 = (2*q1r < len) ? (1.0f / O[8][2]) : 0.0f;
#pragma unroll
    for (int nt = 0; nt < 8; nt++) {
        int col = h*HD_ + nt*8 + 2*c;
        *(float2*)&out[((size_t)(b*SP_ + q0r))*(NH_*HD_) + col] =
            make_float2(O[nt][0]*inv0, O[nt][1]*inv0);
        *(float2*)&out[((size_t)(b*SP_ + q1r))*(NH_*HD_) + col] =
            make_float2(O[nt][2]*inv1, O[nt][3]*inv1);
    }
}

// ---------------- launcher ----------------------------------------------------
extern "C" void kernel_launch(void* const* d_in, const int* in_sizes, int n_in,
                              void* d_out, int out_size) {
    const float* hidden = (const float*)d_in[0];
    const void*  mask   = d_in[1];
    const float* W      = (const float*)d_in[2];
    const float* bias   = (const float*)d_in[3];
    float* out = (float*)d_out;

    cvtlen_kernel<<<(A4_ + W4_ + RT_) / 256, 256>>>(hidden, W, mask);

    cudaFuncSetAttribute(qkv_gemm_h, cudaFuncAttributeMaxDynamicSharedMemorySize, GEMM_SMEM);
    dim3 gg(NQKV_/128, (B_*S_)/128);   // (24, 128)
    qkv_gemm_h<<<gg, 256, GEMM_SMEM>>>(bias);

    cudaFuncSetAttribute(attn_h, cudaFuncAttributeMaxDynamicSharedMemorySize, ATTN_SMEM);
    dim3 ga(SP_/128, NH_, B_);
    attn_h<<<ga, 256, ATTN_SMEM>>>(out);
}

// round 12
// speedup vs baseline: 3.4265x; 1.0373x over previous
#include <cuda_runtime.h>
#include <cuda_fp16.h>
#include <cstdint>
#include <math.h>

#define B_    8
#define S_    2048
#define HID_  1024
#define NH_   16
#define HD_   64
#define SP_   1024
#define NQKV_ 3072
#define QSCALE 0.18033688f   // 0.125 * log2(e)

// ---------------- scratch ----------------------------------------------------
__device__ __half g_ah[B_*S_*HID_];       // half hidden
__device__ __half g_wh[NQKV_*HID_];       // half Wqkv
__device__ float  g_q [B_*S_*HID_];       // q pre-pool f32
__device__ __half g_kh[B_*NH_*S_*HD_];    // roped K half
__device__ __half g_vh[B_*NH_*S_*HD_];    // V half
__device__ float2 g_rope[S_*32];          // (cos, sin) per (pos, freq)
__device__ int    g_len[B_];

// ---------------- helpers -----------------------------------------------------
__device__ __forceinline__ void mma_f16(float* d,
        unsigned a0, unsigned a1, unsigned a2, unsigned a3,
        unsigned b0, unsigned b1) {
    asm volatile("mma.sync.aligned.m16n8k16.row.col.f32.f16.f16.f32 "
        "{%0,%1,%2,%3},{%4,%5,%6,%7},{%8,%9},{%0,%1,%2,%3};\n"
        : "+f"(d[0]), "+f"(d[1]), "+f"(d[2]), "+f"(d[3])
        : "r"(a0), "r"(a1), "r"(a2), "r"(a3), "r"(b0), "r"(b1));
}
__device__ __forceinline__ unsigned pk(float lo, float hi) {
    __half2 h = __floats2half2_rn(lo, hi);
    return *reinterpret_cast<unsigned*>(&h);
}
__device__ __forceinline__ unsigned ex2h2(unsigned x) {
    unsigned r; asm("ex2.approx.f16x2 %0, %1;" : "=r"(r) : "r"(x)); return r;
}
__device__ __forceinline__ uint32_t smem_u32(const void* p) {
    uint32_t a;
    asm("{ .reg .u64 t; cvta.to.shared.u64 t, %1; cvt.u32.u64 %0, t; }"
        : "=r"(a) : "l"(p));
    return a;
}
__device__ __forceinline__ void cp16(uint32_t saddr, const void* gptr) {
    asm volatile("cp.async.cg.shared.global [%0], [%1], 16;"
                 :: "r"(saddr), "l"(gptr));
}
__device__ __forceinline__ void cp_commit() { asm volatile("cp.async.commit_group;"); }
template <int N>
__device__ __forceinline__ void cp_wait() {
    asm volatile("cp.async.wait_group %0;" :: "n"(N));
}
__device__ __forceinline__ void ldsm4(unsigned& r0, unsigned& r1, unsigned& r2,
                                      unsigned& r3, uint32_t addr) {
    asm volatile("ldmatrix.sync.aligned.m8n8.x4.shared.b16 {%0,%1,%2,%3}, [%4];"
        : "=r"(r0), "=r"(r1), "=r"(r2), "=r"(r3) : "r"(addr));
}
__device__ __forceinline__ void ldsm4t(unsigned& r0, unsigned& r1, unsigned& r2,
                                       unsigned& r3, uint32_t addr) {
    asm volatile("ldmatrix.sync.aligned.m8n8.x4.trans.shared.b16 {%0,%1,%2,%3}, [%4];"
        : "=r"(r0), "=r"(r1), "=r"(r2), "=r"(r3) : "r"(addr));
}

// ---------------- kernel 1: half pre-convert + rope table + lengths -----------
#define A4_ (B_*S_*HID_/4)
#define W4_ (NQKV_*HID_/4)
#define RT_ (S_*32)
__global__ void cvtlen_kernel(const float* __restrict__ hidden,
                              const float* __restrict__ W,
                              const void*  __restrict__ mask) {
    int i = blockIdx.x * 256 + threadIdx.x;
    if (i < A4_) {
        float4 v = ((const float4*)hidden)[i];
        ((uint2*)g_ah)[i] = make_uint2(pk(v.x, v.y), pk(v.z, v.w));
    } else if (i < A4_ + W4_) {
        int j = i - A4_;
        float4 v = ((const float4*)W)[j];
        ((uint2*)g_wh)[j] = make_uint2(pk(v.x, v.y), pk(v.z, v.w));
    } else {
        int e = i - A4_ - W4_;
        if (e < RT_) {
            int s = e >> 5, ir = e & 31;
            float theta = __expf(-(float)ir * (9.210340371976184f / 32.0f));
            float sn, cs;
            sincosf((float)s * theta, &sn, &cs);
            g_rope[e] = make_float2(cs, sn);
        }
    }
    if (blockIdx.x == 0) {
        __shared__ int sred[256];
        const int* mi = (const int*)mask;
        int w = mi[16];
        int mode = (w == 1) ? 0 : ((w == 0x3F800000) ? 1 : 2);
        for (int b = 0; b < B_; b++) {
            int cnt = 0;
            for (int s = threadIdx.x; s < S_; s += 256) {
                int v;
                if (mode == 0)      v = (mi[b*S_+s] != 0);
                else if (mode == 1) v = (((const float*)mask)[b*S_+s] != 0.0f);
                else                v = (((const unsigned char*)mask)[b*S_+s] != 0);
                cnt += v;
            }
            sred[threadIdx.x] = cnt;
            __syncthreads();
            for (int st = 128; st > 0; st >>= 1) {
                if (threadIdx.x < st) sred[threadIdx.x] += sred[threadIdx.x + st];
                __syncthreads();
            }
            if (threadIdx.x == 0) g_len[b] = sred[0];
            __syncthreads();
        }
    }
}

// ---------------- kernel 2: QKV GEMM fp16, 128x128 tile, BK=64, 3-stage -------
// 256 threads = 8 warps (2x4), warp 64x32, 2 CTAs/SM.
// Early-exit: M-block rows are 128 contiguous s of one batch; if s0 >= len[b],
// nothing downstream ever reads these outputs (attn ntiles/mask + q_mask).
#define AST_H (128*72)              // halfs per stage (pitch 72)
#define BSTART (3*AST_H)
#define GEMM_SMEM (6*AST_H*2)       // 110592 B
__global__ __launch_bounds__(256, 2) void qkv_gemm_h(const float* __restrict__ bias) {
    const int bm = blockIdx.y, bn = blockIdx.x;
    {
        int bb0 = (bm*128) >> 11;
        int s00 = (bm*128) & 2047;
        if (s00 >= g_len[bb0]) return;     // dead rows: outputs never read
    }
    extern __shared__ __half hs[];
    const uint32_t sb = smem_u32(hs);
    const int tid = threadIdx.x, warp = tid >> 5, lane = tid & 31;
    const int wm = warp >> 2, wn = warp & 3;
    const int g = lane >> 2, c = lane & 3;
    const __half* Ab = g_ah + (size_t)bm * 128 * HID_;
    const __half* Wb = g_wh + (size_t)bn * 128 * HID_;

#define GISSUE(st, kt) do {                                                        \
        _Pragma("unroll")                                                          \
        for (int ii = 0; ii < 8; ii++) {                                           \
            int e = tid + ii*256;                                                  \
            if (e < 1024) {                                                        \
                int row = e >> 3, ch = e & 7;                                      \
                cp16(sb + ((st)*AST_H + row*72 + ch*8)*2,                          \
                     Ab + (size_t)row*HID_ + (kt)*64 + ch*8);                      \
            } else {                                                               \
                int e2 = e - 1024;                                                 \
                int row = e2 >> 3, ch = e2 & 7;                                    \
                cp16(sb + (BSTART + (st)*AST_H + row*72 + ch*8)*2,                 \
                     Wb + (size_t)row*HID_ + (kt)*64 + ch*8);                      \
            }                                                                      \
        }                                                                          \
    } while (0)

    float acc[4][4][4];
#pragma unroll
    for (int i = 0; i < 4; i++)
#pragma unroll
        for (int j = 0; j < 4; j++)
#pragma unroll
            for (int r = 0; r < 4; r++) acc[i][j][r] = 0.0f;

    GISSUE(0, 0); cp_commit();
    GISSUE(1, 1); cp_commit();

    const int l8  = ((lane >> 3) & 1) * 8;
    const int l16 = ((lane >> 4) & 1) * 8;
    for (int kt = 0; kt < 16; kt++) {
        if (kt + 1 < 16) cp_wait<1>(); else cp_wait<0>();
        __syncthreads();
        if (kt + 2 < 16) { GISSUE((kt + 2) % 3, kt + 2); cp_commit(); }

        const uint32_t abase = sb + ((kt % 3) * AST_H) * 2;
        const uint32_t bbase = sb + (BSTART + (kt % 3) * AST_H) * 2;
#pragma unroll
        for (int ks = 0; ks < 4; ks++) {
            unsigned a[4][4], bf[4][2];
#pragma unroll
            for (int i = 0; i < 4; i++) {
                uint32_t ad = abase +
                    ((wm*64 + i*16 + (lane&7) + l8)*72 + ks*16 + l16)*2;
                ldsm4(a[i][0], a[i][1], a[i][2], a[i][3], ad);
            }
#pragma unroll
            for (int jp = 0; jp < 2; jp++) {
                uint32_t bd = bbase +
                    ((wn*32 + jp*16 + (lane&7) + l16)*72 + ks*16 + l8)*2;
                ldsm4(bf[2*jp][0], bf[2*jp][1], bf[2*jp+1][0], bf[2*jp+1][1], bd);
            }
#pragma unroll
            for (int i = 0; i < 4; i++)
#pragma unroll
                for (int j = 0; j < 4; j++)
                    mma_f16(acc[i][j], a[i][0], a[i][1], a[i][2], a[i][3],
                            bf[j][0], bf[j][1]);
        }
    }

    // epilogue: bias; q -> f32 staging; K -> RoPE (table) -> half; V -> half
#pragma unroll
    for (int i = 0; i < 4; i++) {
#pragma unroll
        for (int hh = 0; hh < 2; hh++) {
            int m = bm*128 + wm*64 + i*16 + hh*8 + g;
            int bb2 = m >> 11;
            int sq = m & 2047;
#pragma unroll
            for (int j = 0; j < 4; j++) {
                int n = bn*128 + wn*32 + j*8 + 2*c;
                float v0 = acc[i][j][hh*2+0] + bias[n];
                float v1 = acc[i][j][hh*2+1] + bias[n+1];
                if (n < 1024) {
                    float* p = &g_q[((size_t)(bb2*S_+sq))*HID_ + n];
                    p[0] = v0; p[1] = v1;
                } else if (n < 2048) {
                    int nn = n - 1024, hd = nn >> 6, dd = nn & 63;
                    float2 cs = g_rope[sq*32 + (dd >> 1)];
                    *(unsigned*)&g_kh[(((size_t)(bb2*NH_+hd))*S_ + sq)*HD_ + dd] =
                        pk(v0*cs.x - v1*cs.y, v1*cs.x + v0*cs.y);
                } else {
                    int nn = n - 2048, hd = nn >> 6, dd = nn & 63;
                    *(unsigned*)&g_vh[(((size_t)(bb2*NH_+hd))*S_ + sq)*HD_ + dd] = pk(v0, v1);
                }
            }
        }
    }
}

// ---------------- kernel 3: flash attention fp16, fused pool+RoPE-Q -----------
// grid (8, NH, B), 256 thr = 8 warps; warp = 16 q-rows x 128 k-cols.
// smem halfs: Q[128][72] @0; K(buf) @9216+buf*18432; V(buf) @18432+buf*18432.
// V pad cols 64-71 hold 1.0h -> PV n-tile 8 accumulates row sums (= l).
// Fully-masked q-tiles (qt*128 >= ceil(len/2)) write zeros and exit.
#define ATTN_SMEM (46080*2)   // 92160 B
__global__ __launch_bounds__(256, 2) void attn_h(float* __restrict__ out) {
    extern __shared__ __half hs[];
    const uint32_t sb = smem_u32(hs);
    const int qt = blockIdx.x, h = blockIdx.y, b = blockIdx.z;
    const int len = g_len[b];
    const int tid = threadIdx.x, warp = tid >> 5, lane = tid & 31;
    const int g = lane >> 2, c = lane & 3;

    // ---- dead q-tile: all rows masked -> write zeros, skip everything ----
    const int plen = (len + 1) >> 1;
    if (qt * 128 >= plen) {
        // cover exactly this tile's output: rows qt*128..qt*128+127, cols h*64..h*64+63
#pragma unroll
        for (int ii = 0; ii < 8; ii++) {
            int e = tid + ii*256;             // 2048 float4 = 128 rows x 16 f4
            int r = e >> 4, c4 = e & 15;
            *(float4*)&out[((size_t)(b*SP_ + qt*128 + r))*(NH_*HD_) + h*HD_ + c4*4] =
                make_float4(0.f, 0.f, 0.f, 0.f);
        }
        return;
    }

    const int l8  = ((lane >> 3) & 1) * 8;
    const int l16 = ((lane >> 4) & 1) * 8;
    const size_t khb = (size_t)(b*NH_+h)*S_*HD_;

#define KVLOAD(buf, kt) do {                                                       \
        _Pragma("unroll")                                                          \
        for (int ii = 0; ii < 8; ii++) {                                           \
            int e = tid + ii*256;                                                  \
            if (e < 1024) {                                                        \
                int row = e >> 3, ch = e & 7;                                      \
                cp16(sb + (9216 + (buf)*18432 + row*72 + ch*8)*2,                  \
                     g_kh + khb + (size_t)((kt)*128+row)*HD_ + ch*8);              \
            } else {                                                               \
                int e2 = e - 1024;                                                 \
                int row = e2 >> 3, ch = e2 & 7;                                    \
                cp16(sb + (18432 + (buf)*18432 + row*72 + ch*8)*2,                 \
                     g_vh + khb + (size_t)((kt)*128+row)*HD_ + ch*8);              \
            }                                                                      \
        }                                                                          \
    } while (0)
    KVLOAD(0, 0);
    cp_commit();

    // fused pool + RoPE + scale for Q tile (overlaps the KV loads above)
#pragma unroll
    for (int ii = 0; ii < 16; ii++) {
        int e = tid + ii*256;                  // 4096 = 128 rows x 32 pairs
        int r = e >> 5, i = e & 31;
        int p = qt*128 + r;
        int s0 = 2 * p;
        int c0 = (s0 < len), c1 = (s0 + 1 < len);
        float norm = (c0 + c1 > 0) ? (float)(c0 + c1) : 1.0f;
        const float* row0 = g_q + ((size_t)(b*S_+s0))*HID_ + h*HD_ + 2*i;
        float2 a = c0 ? *(const float2*)row0 : make_float2(0.f, 0.f);
        float2 d = c1 ? *(const float2*)(row0 + HID_) : make_float2(0.f, 0.f);
        float x0 = (a.x + d.x) / norm;
        float x1 = (a.y + d.y) / norm;
        float2 cs = g_rope[p*32 + i];
        *(unsigned*)&hs[r*72 + 2*i] =
            pk((x0*cs.x - x1*cs.y)*QSCALE, (x1*cs.x + x0*cs.y)*QSCALE);
    }
    // ones-pads for both V buffers
#pragma unroll
    for (int ii = 0; ii < 4; ii++) {
        int e = tid + ii*256;                  // 1024 words: 2 bufs x 128 rows x 4
        int bf = e >> 9, row = (e >> 2) & 127, u = e & 3;
        *(unsigned*)&hs[18432 + bf*18432 + row*72 + 64 + u*2] = 0x3C003C00u;
    }

    float O[9][4];
    float m0 = -1e30f, m1 = -1e30f;
#pragma unroll
    for (int nt = 0; nt < 9; nt++)
#pragma unroll
        for (int r = 0; r < 4; r++) O[nt][r] = 0.0f;

    const int ntiles = (len + 127) >> 7;
    int buf = 0;

    for (int kt = 0; kt < ntiles; kt++) {
        if (kt + 1 < ntiles) { KVLOAD(buf ^ 1, kt + 1); cp_commit(); cp_wait<1>(); }
        else cp_wait<0>();
        __syncthreads();

        // ---- S = Q K^T  (all frags via ldmatrix.x4) ----
        float s[16][4];
#pragma unroll
        for (int nt = 0; nt < 16; nt++)
#pragma unroll
            for (int r = 0; r < 4; r++) s[nt][r] = 0.0f;

        const int kH = 9216 + buf*18432;
#pragma unroll
        for (int ks = 0; ks < 4; ks++) {
            uint32_t ad = sb + ((warp*16 + (lane&7) + l8)*72 + ks*16 + l16)*2;
            unsigned a0, a1, a2, a3;
            ldsm4(a0, a1, a2, a3, ad);
#pragma unroll
            for (int ntp = 0; ntp < 8; ntp++) {
                uint32_t bd = sb + (kH + (ntp*16 + (lane&7) + l16)*72 + ks*16 + l8)*2;
                unsigned b0, b1, b2, b3;
                ldsm4(b0, b1, b2, b3, bd);
                mma_f16(s[2*ntp],   a0, a1, a2, a3, b0, b1);
                mma_f16(s[2*ntp+1], a0, a1, a2, a3, b2, b3);
            }
        }

        // ---- mask partial tile ----
        if (kt == ntiles - 1 && (len & 127)) {
#pragma unroll
            for (int nt = 0; nt < 16; nt++)
#pragma unroll
                for (int cc = 0; cc < 2; cc++) {
                    int kcol = kt*128 + nt*8 + 2*c + cc;
                    if (kcol >= len) { s[nt][cc] = -1e30f; s[nt][2+cc] = -1e30f; }
                }
        }

        // ---- online max + corr ----
        float mx0 = -1e30f, mx1 = -1e30f;
#pragma unroll
        for (int nt = 0; nt < 16; nt++) {
            mx0 = fmaxf(mx0, fmaxf(s[nt][0], s[nt][1]));
            mx1 = fmaxf(mx1, fmaxf(s[nt][2], s[nt][3]));
        }
        mx0 = fmaxf(mx0, __shfl_xor_sync(0xffffffffu, mx0, 1));
        mx0 = fmaxf(mx0, __shfl_xor_sync(0xffffffffu, mx0, 2));
        mx1 = fmaxf(mx1, __shfl_xor_sync(0xffffffffu, mx1, 1));
        mx1 = fmaxf(mx1, __shfl_xor_sync(0xffffffffu, mx1, 2));
        float mn0 = fmaxf(m0, mx0), mn1 = fmaxf(m1, mx1);
        float cr0 = exp2f(m0 - mn0), cr1 = exp2f(m1 - mn1);
        m0 = mn0; m1 = mn1;

        // ---- exp in fp16x2 (packed = PV a-frags) ----
        unsigned ph[16][2];
#pragma unroll
        for (int nt = 0; nt < 16; nt++) {
            ph[nt][0] = ex2h2(pk(s[nt][0] - mn0, s[nt][1] - mn0));
            ph[nt][1] = ex2h2(pk(s[nt][2] - mn1, s[nt][3] - mn1));
        }
#pragma unroll
        for (int nt = 0; nt < 9; nt++) {
            O[nt][0] *= cr0; O[nt][1] *= cr0;
            O[nt][2] *= cr1; O[nt][3] *= cr1;
        }

        // ---- O += P V  (V + ones column via ldmatrix.x4.trans) ----
        const int vH = 18432 + buf*18432;
#pragma unroll
        for (int t = 0; t < 4; t++) {
            unsigned pa0 = ph[4*t][0],   pa1 = ph[4*t][1];
            unsigned pa2 = ph[4*t+1][0], pa3 = ph[4*t+1][1];
            unsigned qa0 = ph[4*t+2][0], qa1 = ph[4*t+2][1];
            unsigned qa2 = ph[4*t+3][0], qa3 = ph[4*t+3][1];
#pragma unroll
            for (int nt = 0; nt < 9; nt++) {
                uint32_t vd = sb + (vH + (t*32 + lane)*72 + nt*8)*2;
                unsigned b0, b1, b2, b3;
                ldsm4t(b0, b1, b2, b3, vd);
                mma_f16(O[nt], pa0, pa1, pa2, pa3, b0, b1);
                mma_f16(O[nt], qa0, qa1, qa2, qa3, b2, b3);
            }
        }
        __syncthreads();
        buf ^= 1;
    }

    // ---- epilogue: l = O[8]; 1/l; q_mask; write ----
    int q0r = qt*128 + warp*16 + g;
    int q1r = q0r + 8;
    float inv0 = (2*q0r < len) ? (1.0f / O[8][0]) : 0.0f;
    float inv1 = (2*q1r < len) ? (1.0f / O[8][2]) : 0.0f;
#pragma unroll
    for (int nt = 0; nt < 8; nt++) {
        int col = h*HD_ + nt*8 + 2*c;
        *(float2*)&out[((size_t)(b*SP_ + q0r))*(NH_*HD_) + col] =
            make_float2(O[nt][0]*inv0, O[nt][1]*inv0);
        *(float2*)&out[((size_t)(b*SP_ + q1r))*(NH_*HD_) + col] =
            make_float2(O[nt][2]*inv1, O[nt][3]*inv1);
    }
}

// ---------------- launcher ----------------------------------------------------
extern "C" void kernel_launch(void* const* d_in, const int* in_sizes, int n_in,
                              void* d_out, int out_size) {
    const float* hidden = (const float*)d_in[0];
    const void*  mask   = d_in[1];
    const float* W      = (const float*)d_in[2];
    const float* bias   = (const float*)d_in[3];
    float* out = (float*)d_out;

    cvtlen_kernel<<<(A4_ + W4_ + RT_) / 256, 256>>>(hidden, W, mask);

    cudaFuncSetAttribute(qkv_gemm_h, cudaFuncAttributeMaxDynamicSharedMemorySize, GEMM_SMEM);
    dim3 gg(NQKV_/128, (B_*S_)/128);   // (24, 128)
    qkv_gemm_h<<<gg, 256, GEMM_SMEM>>>(bias);

    cudaFuncSetAttribute(attn_h, cudaFuncAttributeMaxDynamicSharedMemorySize, ATTN_SMEM);
    dim3 ga(SP_/128, NH_, B_);
    attn_h<<<ga, 256, ATTN_SMEM>>>(out);
}

// round 13
// speedup vs baseline: 3.4364x; 1.0029x over previous
#include <cuda_runtime.h>
#include <cuda_fp16.h>
#include <cstdint>
#include <math.h>

#define B_    8
#define S_    2048
#define HID_  1024
#define NH_   16
#define HD_   64
#define SP_   1024
#define NQKV_ 3072
#define QSCALE 0.18033688f   // 0.125 * log2(e)

// ---------------- scratch ----------------------------------------------------
__device__ __half g_ah[B_*S_*HID_];       // half hidden
__device__ __half g_wh[NQKV_*HID_];       // half Wqkv
__device__ __half g_qs[B_*S_*HID_];       // q pre-pool (half)
__device__ __half g_kh[B_*NH_*S_*HD_];    // roped K half
__device__ __half g_vh[B_*NH_*S_*HD_];    // V half
__device__ float2 g_rope[S_*32];          // (cos, sin) per (pos, freq)
__device__ int    g_len[B_];

// ---------------- helpers -----------------------------------------------------
__device__ __forceinline__ void mma_f16(float* d,
        unsigned a0, unsigned a1, unsigned a2, unsigned a3,
        unsigned b0, unsigned b1) {
    asm volatile("mma.sync.aligned.m16n8k16.row.col.f32.f16.f16.f32 "
        "{%0,%1,%2,%3},{%4,%5,%6,%7},{%8,%9},{%0,%1,%2,%3};\n"
        : "+f"(d[0]), "+f"(d[1]), "+f"(d[2]), "+f"(d[3])
        : "r"(a0), "r"(a1), "r"(a2), "r"(a3), "r"(b0), "r"(b1));
}
__device__ __forceinline__ unsigned pk(float lo, float hi) {
    __half2 h = __floats2half2_rn(lo, hi);
    return *reinterpret_cast<unsigned*>(&h);
}
__device__ __forceinline__ float2 up(unsigned x) {
    return __half22float2(*reinterpret_cast<__half2*>(&x));
}
__device__ __forceinline__ unsigned ex2h2(unsigned x) {
    unsigned r; asm("ex2.approx.f16x2 %0, %1;" : "=r"(r) : "r"(x)); return r;
}
__device__ __forceinline__ uint32_t smem_u32(const void* p) {
    uint32_t a;
    asm("{ .reg .u64 t; cvta.to.shared.u64 t, %1; cvt.u32.u64 %0, t; }"
        : "=r"(a) : "l"(p));
    return a;
}
__device__ __forceinline__ void cp16(uint32_t saddr, const void* gptr) {
    asm volatile("cp.async.cg.shared.global [%0], [%1], 16;"
                 :: "r"(saddr), "l"(gptr));
}
__device__ __forceinline__ void cp_commit() { asm volatile("cp.async.commit_group;"); }
template <int N>
__device__ __forceinline__ void cp_wait() {
    asm volatile("cp.async.wait_group %0;" :: "n"(N));
}
__device__ __forceinline__ void ldsm4(unsigned& r0, unsigned& r1, unsigned& r2,
                                      unsigned& r3, uint32_t addr) {
    asm volatile("ldmatrix.sync.aligned.m8n8.x4.shared.b16 {%0,%1,%2,%3}, [%4];"
        : "=r"(r0), "=r"(r1), "=r"(r2), "=r"(r3) : "r"(addr));
}
__device__ __forceinline__ void ldsm4t(unsigned& r0, unsigned& r1, unsigned& r2,
                                       unsigned& r3, uint32_t addr) {
    asm volatile("ldmatrix.sync.aligned.m8n8.x4.trans.shared.b16 {%0,%1,%2,%3}, [%4];"
        : "=r"(r0), "=r"(r1), "=r"(r2), "=r"(r3) : "r"(addr));
}

// ---------------- kernel 1: half pre-convert + rope table + lengths -----------
#define A4_ (B_*S_*HID_/4)
#define W4_ (NQKV_*HID_/4)
#define RT_ (S_*32)
__global__ void cvtlen_kernel(const float* __restrict__ hidden,
                              const float* __restrict__ W,
                              const void*  __restrict__ mask) {
    int i = blockIdx.x * 256 + threadIdx.x;
    if (i < A4_) {
        float4 v = ((const float4*)hidden)[i];
        ((uint2*)g_ah)[i] = make_uint2(pk(v.x, v.y), pk(v.z, v.w));
    } else if (i < A4_ + W4_) {
        int j = i - A4_;
        float4 v = ((const float4*)W)[j];
        ((uint2*)g_wh)[j] = make_uint2(pk(v.x, v.y), pk(v.z, v.w));
    } else {
        int e = i - A4_ - W4_;
        if (e < RT_) {
            int s = e >> 5, ir = e & 31;
            float theta = __expf(-(float)ir * (9.210340371976184f / 32.0f));
            float sn, cs;
            sincosf((float)s * theta, &sn, &cs);
            g_rope[e] = make_float2(cs, sn);
        }
    }
    if (blockIdx.x == 0) {
        __shared__ int sred[256];
        const int* mi = (const int*)mask;
        int w = mi[16];
        int mode = (w == 1) ? 0 : ((w == 0x3F800000) ? 1 : 2);
        for (int b = 0; b < B_; b++) {
            int cnt = 0;
            for (int s = threadIdx.x; s < S_; s += 256) {
                int v;
                if (mode == 0)      v = (mi[b*S_+s] != 0);
                else if (mode == 1) v = (((const float*)mask)[b*S_+s] != 0.0f);
                else                v = (((const unsigned char*)mask)[b*S_+s] != 0);
                cnt += v;
            }
            sred[threadIdx.x] = cnt;
            __syncthreads();
            for (int st = 128; st > 0; st >>= 1) {
                if (threadIdx.x < st) sred[threadIdx.x] += sred[threadIdx.x + st];
                __syncthreads();
            }
            if (threadIdx.x == 0) g_len[b] = sred[0];
            __syncthreads();
        }
    }
}

// ---------------- kernel 2: QKV GEMM fp16, 128x128 tile, BK=64, 3-stage -------
// 256 threads = 8 warps (2x4), warp 64x32, 2 CTAs/SM. Dead M-blocks exit.
#define AST_H (128*72)              // halfs per stage (pitch 72)
#define BSTART (3*AST_H)
#define GEMM_SMEM (6*AST_H*2)       // 110592 B
__global__ __launch_bounds__(256, 2) void qkv_gemm_h(const float* __restrict__ bias) {
    const int bm = blockIdx.y, bn = blockIdx.x;
    {
        int bb0 = (bm*128) >> 11;
        int s00 = (bm*128) & 2047;
        if (s00 >= g_len[bb0]) return;     // dead rows: outputs never read
    }
    extern __shared__ __half hs[];
    const uint32_t sb = smem_u32(hs);
    const int tid = threadIdx.x, warp = tid >> 5, lane = tid & 31;
    const int wm = warp >> 2, wn = warp & 3;
    const int g = lane >> 2, c = lane & 3;
    const __half* Ab = g_ah + (size_t)bm * 128 * HID_;
    const __half* Wb = g_wh + (size_t)bn * 128 * HID_;

#define GISSUE(st, kt) do {                                                        \
        _Pragma("unroll")                                                          \
        for (int ii = 0; ii < 8; ii++) {                                           \
            int e = tid + ii*256;                                                  \
            if (e < 1024) {                                                        \
                int row = e >> 3, ch = e & 7;                                      \
                cp16(sb + ((st)*AST_H + row*72 + ch*8)*2,                          \
                     Ab + (size_t)row*HID_ + (kt)*64 + ch*8);                      \
            } else {                                                               \
                int e2 = e - 1024;                                                 \
                int row = e2 >> 3, ch = e2 & 7;                                    \
                cp16(sb + (BSTART + (st)*AST_H + row*72 + ch*8)*2,                 \
                     Wb + (size_t)row*HID_ + (kt)*64 + ch*8);                      \
            }                                                                      \
        }                                                                          \
    } while (0)

    float acc[4][4][4];
#pragma unroll
    for (int i = 0; i < 4; i++)
#pragma unroll
        for (int j = 0; j < 4; j++)
#pragma unroll
            for (int r = 0; r < 4; r++) acc[i][j][r] = 0.0f;

    GISSUE(0, 0); cp_commit();
    GISSUE(1, 1); cp_commit();

    const int l8  = ((lane >> 3) & 1) * 8;
    const int l16 = ((lane >> 4) & 1) * 8;
    for (int kt = 0; kt < 16; kt++) {
        if (kt + 1 < 16) cp_wait<1>(); else cp_wait<0>();
        __syncthreads();
        if (kt + 2 < 16) { GISSUE((kt + 2) % 3, kt + 2); cp_commit(); }

        const uint32_t abase = sb + ((kt % 3) * AST_H) * 2;
        const uint32_t bbase = sb + (BSTART + (kt % 3) * AST_H) * 2;
#pragma unroll
        for (int ks = 0; ks < 4; ks++) {
            unsigned a[4][4], bf[4][2];
#pragma unroll
            for (int i = 0; i < 4; i++) {
                uint32_t ad = abase +
                    ((wm*64 + i*16 + (lane&7) + l8)*72 + ks*16 + l16)*2;
                ldsm4(a[i][0], a[i][1], a[i][2], a[i][3], ad);
            }
#pragma unroll
            for (int jp = 0; jp < 2; jp++) {
                uint32_t bd = bbase +
                    ((wn*32 + jp*16 + (lane&7) + l16)*72 + ks*16 + l8)*2;
                ldsm4(bf[2*jp][0], bf[2*jp][1], bf[2*jp+1][0], bf[2*jp+1][1], bd);
            }
#pragma unroll
            for (int i = 0; i < 4; i++)
#pragma unroll
                for (int j = 0; j < 4; j++)
                    mma_f16(acc[i][j], a[i][0], a[i][1], a[i][2], a[i][3],
                            bf[j][0], bf[j][1]);
        }
    }

    // epilogue: bias; q -> half staging; K -> RoPE (table) -> half; V -> half
#pragma unroll
    for (int i = 0; i < 4; i++) {
#pragma unroll
        for (int hh = 0; hh < 2; hh++) {
            int m = bm*128 + wm*64 + i*16 + hh*8 + g;
            int bb2 = m >> 11;
            int sq = m & 2047;
#pragma unroll
            for (int j = 0; j < 4; j++) {
                int n = bn*128 + wn*32 + j*8 + 2*c;
                float v0 = acc[i][j][hh*2+0] + bias[n];
                float v1 = acc[i][j][hh*2+1] + bias[n+1];
                if (n < 1024) {
                    *(unsigned*)&g_qs[((size_t)(bb2*S_+sq))*HID_ + n] = pk(v0, v1);
                } else if (n < 2048) {
                    int nn = n - 1024, hd = nn >> 6, dd = nn & 63;
                    float2 cs = g_rope[sq*32 + (dd >> 1)];
                    *(unsigned*)&g_kh[(((size_t)(bb2*NH_+hd))*S_ + sq)*HD_ + dd] =
                        pk(v0*cs.x - v1*cs.y, v1*cs.x + v0*cs.y);
                } else {
                    int nn = n - 2048, hd = nn >> 6, dd = nn & 63;
                    *(unsigned*)&g_vh[(((size_t)(bb2*NH_+hd))*S_ + sq)*HD_ + dd] = pk(v0, v1);
                }
            }
        }
    }
}

// ---------------- kernel 3: flash attention fp16, fused pool+RoPE-Q -----------
// grid (8, NH, B), 256 thr = 8 warps; warp = 16 q-rows x 128 k-cols.
// smem halfs: Q[128][72] @0; K(buf) @9216+buf*18432; V(buf) @18432+buf*18432.
// Row sums in f32 (FMA pipe) — tensor pipe is the saturated resource.
#define ATTN_SMEM (46080*2)   // 92160 B
__global__ __launch_bounds__(256, 2) void attn_h(float* __restrict__ out) {
    extern __shared__ __half hs[];
    const uint32_t sb = smem_u32(hs);
    const int qt = blockIdx.x, h = blockIdx.y, b = blockIdx.z;
    const int len = g_len[b];
    const int tid = threadIdx.x, warp = tid >> 5, lane = tid & 31;
    const int g = lane >> 2, c = lane & 3;

    // ---- dead q-tile: all rows masked -> write zeros, skip everything ----
    const int plen = (len + 1) >> 1;
    if (qt * 128 >= plen) {
#pragma unroll
        for (int ii = 0; ii < 8; ii++) {
            int e = tid + ii*256;             // 2048 float4 = 128 rows x 16 f4
            int r = e >> 4, c4 = e & 15;
            *(float4*)&out[((size_t)(b*SP_ + qt*128 + r))*(NH_*HD_) + h*HD_ + c4*4] =
                make_float4(0.f, 0.f, 0.f, 0.f);
        }
        return;
    }

    const int l8  = ((lane >> 3) & 1) * 8;
    const int l16 = ((lane >> 4) & 1) * 8;
    const size_t khb = (size_t)(b*NH_+h)*S_*HD_;

#define KVLOAD(buf, kt) do {                                                       \
        _Pragma("unroll")                                                          \
        for (int ii = 0; ii < 8; ii++) {                                           \
            int e = tid + ii*256;                                                  \
            if (e < 1024) {                                                        \
                int row = e >> 3, ch = e & 7;                                      \
                cp16(sb + (9216 + (buf)*18432 + row*72 + ch*8)*2,                  \
                     g_kh + khb + (size_t)((kt)*128+row)*HD_ + ch*8);              \
            } else {                                                               \
                int e2 = e - 1024;                                                 \
                int row = e2 >> 3, ch = e2 & 7;                                    \
                cp16(sb + (18432 + (buf)*18432 + row*72 + ch*8)*2,                 \
                     g_vh + khb + (size_t)((kt)*128+row)*HD_ + ch*8);              \
            }                                                                      \
        }                                                                          \
    } while (0)
    KVLOAD(0, 0);
    cp_commit();

    // fused pool + RoPE + scale for Q tile (overlaps the KV loads above)
#pragma unroll
    for (int ii = 0; ii < 16; ii++) {
        int e = tid + ii*256;                  // 4096 = 128 rows x 32 pairs
        int r = e >> 5, i = e & 31;
        int p = qt*128 + r;
        int s0 = 2 * p;
        int c0 = (s0 < len), c1 = (s0 + 1 < len);
        float norm = (c0 + c1 > 0) ? (float)(c0 + c1) : 1.0f;
        const __half* row0 = g_qs + ((size_t)(b*S_+s0))*HID_ + h*HD_ + 2*i;
        float2 a = c0 ? __half22float2(*(const __half2*)row0) : make_float2(0.f, 0.f);
        float2 d = c1 ? __half22float2(*(const __half2*)(row0 + HID_)) : make_float2(0.f, 0.f);
        float x0 = (a.x + d.x) / norm;
        float x1 = (a.y + d.y) / norm;
        float2 cs = g_rope[p*32 + i];
        *(unsigned*)&hs[r*72 + 2*i] =
            pk((x0*cs.x - x1*cs.y)*QSCALE, (x1*cs.x + x0*cs.y)*QSCALE);
    }

    float O[8][4];
    float m0 = -1e30f, m1 = -1e30f, lq0 = 0.0f, lq1 = 0.0f;
#pragma unroll
    for (int nt = 0; nt < 8; nt++)
#pragma unroll
        for (int r = 0; r < 4; r++) O[nt][r] = 0.0f;

    const int ntiles = (len + 127) >> 7;
    int buf = 0;

    for (int kt = 0; kt < ntiles; kt++) {
        if (kt + 1 < ntiles) { KVLOAD(buf ^ 1, kt + 1); cp_commit(); cp_wait<1>(); }
        else cp_wait<0>();
        __syncthreads();

        // ---- S = Q K^T  (all frags via ldmatrix.x4) ----
        float s[16][4];
#pragma unroll
        for (int nt = 0; nt < 16; nt++)
#pragma unroll
            for (int r = 0; r < 4; r++) s[nt][r] = 0.0f;

        const int kH = 9216 + buf*18432;
#pragma unroll
        for (int ks = 0; ks < 4; ks++) {
            uint32_t ad = sb + ((warp*16 + (lane&7) + l8)*72 + ks*16 + l16)*2;
            unsigned a0, a1, a2, a3;
            ldsm4(a0, a1, a2, a3, ad);
#pragma unroll
            for (int ntp = 0; ntp < 8; ntp++) {
                uint32_t bd = sb + (kH + (ntp*16 + (lane&7) + l16)*72 + ks*16 + l8)*2;
                unsigned b0, b1, b2, b3;
                ldsm4(b0, b1, b2, b3, bd);
                mma_f16(s[2*ntp],   a0, a1, a2, a3, b0, b1);
                mma_f16(s[2*ntp+1], a0, a1, a2, a3, b2, b3);
            }
        }

        // ---- mask partial tile ----
        if (kt == ntiles - 1 && (len & 127)) {
#pragma unroll
            for (int nt = 0; nt < 16; nt++)
#pragma unroll
                for (int cc = 0; cc < 2; cc++) {
                    int kcol = kt*128 + nt*8 + 2*c + cc;
                    if (kcol >= len) { s[nt][cc] = -1e30f; s[nt][2+cc] = -1e30f; }
                }
        }

        // ---- online max + corr ----
        float mx0 = -1e30f, mx1 = -1e30f;
#pragma unroll
        for (int nt = 0; nt < 16; nt++) {
            mx0 = fmaxf(mx0, fmaxf(s[nt][0], s[nt][1]));
            mx1 = fmaxf(mx1, fmaxf(s[nt][2], s[nt][3]));
        }
        mx0 = fmaxf(mx0, __shfl_xor_sync(0xffffffffu, mx0, 1));
        mx0 = fmaxf(mx0, __shfl_xor_sync(0xffffffffu, mx0, 2));
        mx1 = fmaxf(mx1, __shfl_xor_sync(0xffffffffu, mx1, 1));
        mx1 = fmaxf(mx1, __shfl_xor_sync(0xffffffffu, mx1, 2));
        float mn0 = fmaxf(m0, mx0), mn1 = fmaxf(m1, mx1);
        float cr0 = exp2f(m0 - mn0), cr1 = exp2f(m1 - mn1);
        m0 = mn0; m1 = mn1;

        // ---- exp in fp16x2 (packed = PV a-frags); f32 row sums of the SAME
        //      fp16 values (num/den consistent) on the idle FMA pipe ----
        unsigned ph[16][2];
        float r0 = 0.0f, r1 = 0.0f;
#pragma unroll
        for (int nt = 0; nt < 16; nt++) {
            ph[nt][0] = ex2h2(pk(s[nt][0] - mn0, s[nt][1] - mn0));
            ph[nt][1] = ex2h2(pk(s[nt][2] - mn1, s[nt][3] - mn1));
            float2 f0 = up(ph[nt][0]);
            float2 f1 = up(ph[nt][1]);
            r0 += f0.x + f0.y;
            r1 += f1.x + f1.y;
        }
        r0 += __shfl_xor_sync(0xffffffffu, r0, 1);
        r0 += __shfl_xor_sync(0xffffffffu, r0, 2);
        r1 += __shfl_xor_sync(0xffffffffu, r1, 1);
        r1 += __shfl_xor_sync(0xffffffffu, r1, 2);
        lq0 = lq0*cr0 + r0;
        lq1 = lq1*cr1 + r1;
#pragma unroll
        for (int nt = 0; nt < 8; nt++) {
            O[nt][0] *= cr0; O[nt][1] *= cr0;
            O[nt][2] *= cr1; O[nt][3] *= cr1;
        }

        // ---- O += P V  (V via ldmatrix.x4.trans) ----
        const int vH = 18432 + buf*18432;
#pragma unroll
        for (int t = 0; t < 4; t++) {
            unsigned pa0 = ph[4*t][0],   pa1 = ph[4*t][1];
            unsigned pa2 = ph[4*t+1][0], pa3 = ph[4*t+1][1];
            unsigned qa0 = ph[4*t+2][0], qa1 = ph[4*t+2][1];
            unsigned qa2 = ph[4*t+3][0], qa3 = ph[4*t+3][1];
#pragma unroll
            for (int nt = 0; nt < 8; nt++) {
                uint32_t vd = sb + (vH + (t*32 + lane)*72 + nt*8)*2;
                unsigned b0, b1, b2, b3;
                ldsm4t(b0, b1, b2, b3, vd);
                mma_f16(O[nt], pa0, pa1, pa2, pa3, b0, b1);
                mma_f16(O[nt], qa0, qa1, qa2, qa3, b2, b3);
            }
        }
        __syncthreads();
        buf ^= 1;
    }

    // ---- epilogue: 1/l; q_mask; write ----
    int q0r = qt*128 + warp*16 + g;
    int q1r = q0r + 8;
    float inv0 = (2*q0r < len) ? (1.0f / lq0) : 0.0f;
    float inv1 = (2*q1r < len) ? (1.0f / lq1) : 0.0f;
#pragma unroll
    for (int nt = 0; nt < 8; nt++) {
        int col = h*HD_ + nt*8 + 2*c;
        *(float2*)&out[((size_t)(b*SP_ + q0r))*(NH_*HD_) + col] =
            make_float2(O[nt][0]*inv0, O[nt][1]*inv0);
        *(float2*)&out[((size_t)(b*SP_ + q1r))*(NH_*HD_) + col] =
            make_float2(O[nt][2]*inv1, O[nt][3]*inv1);
    }
}

// ---------------- launcher ----------------------------------------------------
extern "C" void kernel_launch(void* const* d_in, const int* in_sizes, int n_in,
                              void* d_out, int out_size) {
    const float* hidden = (const float*)d_in[0];
    const void*  mask   = d_in[1];
    const float* W      = (const float*)d_in[2];
    const float* bias   = (const float*)d_in[3];
    float* out = (float*)d_out;

    cvtlen_kernel<<<(A4_ + W4_ + RT_) / 256, 256>>>(hidden, W, mask);

    cudaFuncSetAttribute(qkv_gemm_h, cudaFuncAttributeMaxDynamicSharedMemorySize, GEMM_SMEM);
    dim3 gg(NQKV_/128, (B_*S_)/128);   // (24, 128)
    qkv_gemm_h<<<gg, 256, GEMM_SMEM>>>(bias);

    cudaFuncSetAttribute(attn_h, cudaFuncAttributeMaxDynamicSharedMemorySize, ATTN_SMEM);
    dim3 ga(SP_/128, NH_, B_);
    attn_h<<<ga, 256, ATTN_SMEM>>>(out);
}